// round 1
// baseline (speedup 1.0000x reference)
#include <cuda_runtime.h>
#include <math.h>

#define SLEN 2048
#define BATCH 4
#define DMODEL 1024
#define NHEAD 16
#define HDIM 64
#define FFDIM 4096
#define NROW (SLEN*BATCH)      /* 8192 */
#define LDAQ (BATCH*DMODEL)    /* 4096: row stride of (s) in [S,B,D] */

// ------------------------- static scratch (no cudaMalloc allowed) -----------
__device__ float g_q  [NROW*DMODEL];
__device__ float g_k  [NROW*DMODEL];
__device__ float g_v  [NROW*DMODEL];
__device__ float g_att[NROW*DMODEL];
__device__ float g_y  [NROW*DMODEL];
__device__ float g_x1 [NROW*DMODEL];
__device__ float g_h  [NROW*FFDIM];
__device__ float g_y2 [NROW*DMODEL];
__device__ float g_p  [268435456];   // [B*H, S, S] = 64*2048*2048 floats (1.07 GB)

// ---------------------------------------------------------------------------
// Generic SGEMM:  C[M,N] = A[M,K] * W[N,K]^T + bias[N]   (optional ReLU)
// BM=BN=128, BK=8, 256 threads, 8x8 per thread. All dims divisible.
// ---------------------------------------------------------------------------
template<bool RELU>
__global__ __launch_bounds__(256, 2)
void gemm_nt(const float* __restrict__ A, const float* __restrict__ W,
             const float* __restrict__ bias, float* __restrict__ C,
             int M, int N, int K)
{
    __shared__ float As[8][132];
    __shared__ float Bs[8][132];
    const int tid  = threadIdx.x;
    const int bm   = blockIdx.y * 128;
    const int bn   = blockIdx.x * 128;
    const int lrow = tid >> 1;
    const int lseg = (tid & 1) * 4;
    const int ty   = tid >> 4;
    const int tx   = tid & 15;

    const float* Ap = A + (size_t)(bm + lrow) * K + lseg;
    const float* Wp = W + (size_t)(bn + lrow) * K + lseg;

    float acc[8][8];
#pragma unroll
    for (int i = 0; i < 8; i++)
#pragma unroll
        for (int j = 0; j < 8; j++) acc[i][j] = 0.f;

    float4 va = *(const float4*)Ap;
    float4 vb = *(const float4*)Wp;

    for (int k0 = 0; k0 < K; k0 += 8) {
        As[lseg+0][lrow] = va.x; As[lseg+1][lrow] = va.y;
        As[lseg+2][lrow] = va.z; As[lseg+3][lrow] = va.w;
        Bs[lseg+0][lrow] = vb.x; Bs[lseg+1][lrow] = vb.y;
        Bs[lseg+2][lrow] = vb.z; Bs[lseg+3][lrow] = vb.w;
        __syncthreads();
        if (k0 + 8 < K) {
            va = *(const float4*)(Ap + k0 + 8);
            vb = *(const float4*)(Wp + k0 + 8);
        }
#pragma unroll
        for (int kk = 0; kk < 8; kk++) {
            float4 a0 = *(const float4*)&As[kk][ty*8];
            float4 a1 = *(const float4*)&As[kk][ty*8+4];
            float4 b0 = *(const float4*)&Bs[kk][tx*8];
            float4 b1 = *(const float4*)&Bs[kk][tx*8+4];
            float a[8] = {a0.x,a0.y,a0.z,a0.w,a1.x,a1.y,a1.z,a1.w};
            float b[8] = {b0.x,b0.y,b0.z,b0.w,b1.x,b1.y,b1.z,b1.w};
#pragma unroll
            for (int i = 0; i < 8; i++)
#pragma unroll
                for (int j = 0; j < 8; j++) acc[i][j] += a[i]*b[j];
        }
        __syncthreads();
    }

    float bvv[8];
#pragma unroll
    for (int j = 0; j < 8; j++) bvv[j] = bias[bn + tx*8 + j];
#pragma unroll
    for (int i = 0; i < 8; i++) {
        const int row = bm + ty*8 + i;
        float* cp = C + (size_t)row * N + bn + tx*8;
        float o[8];
#pragma unroll
        for (int j = 0; j < 8; j++) {
            float v = acc[i][j] + bvv[j];
            o[j] = RELU ? fmaxf(v, 0.f) : v;
        }
        *(float4*)(cp)     = make_float4(o[0],o[1],o[2],o[3]);
        *(float4*)(cp + 4) = make_float4(o[4],o[5],o[6],o[7]);
    }
}

// ---------------------------------------------------------------------------
// Scores: for each (b,h):  P[s,t] = sum_d q(s,b,h,d) * k(t,b,h,d)   (raw dot)
// grid (S/128, S/128, B*H). Mask+scale applied in softmax.
// ---------------------------------------------------------------------------
__global__ __launch_bounds__(256, 2)
void attn_scores(const float* __restrict__ Q, const float* __restrict__ Km,
                 float* __restrict__ P)
{
    __shared__ float As[8][132];
    __shared__ float Bs[8][132];
    const int tid  = threadIdx.x;
    const int bh   = blockIdx.z;
    const int b    = bh >> 4, h = bh & 15;
    const float* qb = Q  + b*DMODEL + h*HDIM;
    const float* kb = Km + b*DMODEL + h*HDIM;
    const int bm   = blockIdx.y * 128;
    const int bn   = blockIdx.x * 128;
    const int lrow = tid >> 1;
    const int lseg = (tid & 1) * 4;
    const int ty   = tid >> 4, tx = tid & 15;

    float acc[8][8];
#pragma unroll
    for (int i = 0; i < 8; i++)
#pragma unroll
        for (int j = 0; j < 8; j++) acc[i][j] = 0.f;

    float4 va = *(const float4*)(qb + (size_t)(bm+lrow)*LDAQ + lseg);
    float4 vb = *(const float4*)(kb + (size_t)(bn+lrow)*LDAQ + lseg);

    for (int k0 = 0; k0 < HDIM; k0 += 8) {
        As[lseg+0][lrow] = va.x; As[lseg+1][lrow] = va.y;
        As[lseg+2][lrow] = va.z; As[lseg+3][lrow] = va.w;
        Bs[lseg+0][lrow] = vb.x; Bs[lseg+1][lrow] = vb.y;
        Bs[lseg+2][lrow] = vb.z; Bs[lseg+3][lrow] = vb.w;
        __syncthreads();
        if (k0 + 8 < HDIM) {
            va = *(const float4*)(qb + (size_t)(bm+lrow)*LDAQ + k0 + 8 + lseg);
            vb = *(const float4*)(kb + (size_t)(bn+lrow)*LDAQ + k0 + 8 + lseg);
        }
#pragma unroll
        for (int kk = 0; kk < 8; kk++) {
            float4 a0 = *(const float4*)&As[kk][ty*8];
            float4 a1 = *(const float4*)&As[kk][ty*8+4];
            float4 b0 = *(const float4*)&Bs[kk][tx*8];
            float4 b1 = *(const float4*)&Bs[kk][tx*8+4];
            float a[8] = {a0.x,a0.y,a0.z,a0.w,a1.x,a1.y,a1.z,a1.w};
            float bb[8]= {b0.x,b0.y,b0.z,b0.w,b1.x,b1.y,b1.z,b1.w};
#pragma unroll
            for (int i = 0; i < 8; i++)
#pragma unroll
                for (int j = 0; j < 8; j++) acc[i][j] += a[i]*bb[j];
        }
        __syncthreads();
    }

    float* pp = P + (size_t)bh * SLEN * SLEN;
#pragma unroll
    for (int i = 0; i < 8; i++) {
        float* cp = pp + (size_t)(bm + ty*8 + i) * SLEN + bn + tx*8;
        *(float4*)(cp)     = make_float4(acc[i][0],acc[i][1],acc[i][2],acc[i][3]);
        *(float4*)(cp + 4) = make_float4(acc[i][4],acc[i][5],acc[i][6],acc[i][7]);
    }
}

// ---------------------------------------------------------------------------
// Masked softmax over key dim, in place. One block per (bh, s) row.
// Mask dtype probed at runtime: byte[S-1]==1 <=> uint8/bool layout
// (for int32 little-endian 0/1 values, byte 2047 is the high byte of elem 511 = 0).
// ---------------------------------------------------------------------------
__global__ void softmax_mask(float* __restrict__ P, const void* __restrict__ mask)
{
    const int bh  = blockIdx.y;
    const int b   = bh >> 4;
    const int row = blockIdx.x;
    float* p = P + (size_t)bh * SLEN * SLEN + (size_t)row * SLEN;

    const unsigned char* m8  = (const unsigned char*)mask;
    const int*           m32 = (const int*)mask;
    const bool isu8 = (m8[SLEN - 1] == 1);

    const int tid = threadIdx.x;
    float vals[8];
    float mx = -INFINITY;
#pragma unroll
    for (int i = 0; i < 8; i++) {
        const int t = tid + i * 256;
        const bool mk = isu8 ? (m8[b*SLEN + t] != 0) : (m32[b*SLEN + t] != 0);
        const float v = mk ? -INFINITY : p[t] * 0.125f;   // 1/sqrt(64)
        vals[i] = v;
        mx = fmaxf(mx, v);
    }

    __shared__ float red[8];
#pragma unroll
    for (int o = 16; o; o >>= 1) mx = fmaxf(mx, __shfl_xor_sync(0xffffffffu, mx, o));
    if ((tid & 31) == 0) red[tid >> 5] = mx;
    __syncthreads();
    float bmax = red[0];
#pragma unroll
    for (int i = 1; i < 8; i++) bmax = fmaxf(bmax, red[i]);
    __syncthreads();

    float ssum = 0.f;
#pragma unroll
    for (int i = 0; i < 8; i++) {
        vals[i] = __expf(vals[i] - bmax);   // exp(-inf)=0 for masked
        ssum += vals[i];
    }
#pragma unroll
    for (int o = 16; o; o >>= 1) ssum += __shfl_xor_sync(0xffffffffu, ssum, o);
    if ((tid & 31) == 0) red[tid >> 5] = ssum;
    __syncthreads();
    float tot = 0.f;
#pragma unroll
    for (int i = 0; i < 8; i++) tot += red[i];
    const float inv = 1.f / tot;

#pragma unroll
    for (int i = 0; i < 8; i++) p[tid + i * 256] = vals[i] * inv;
}

// ---------------------------------------------------------------------------
// PV: for each (b,h): O[s,d] = sum_t P[s,t] * v(t,b,h,d).  BM=128, BN=64, BK=16.
// grid (S/128, B*H). Output written into [s*B+b, h*64+d] layout.
// ---------------------------------------------------------------------------
__global__ __launch_bounds__(256, 2)
void attn_pv(const float* __restrict__ P, const float* __restrict__ V,
             float* __restrict__ O)
{
    __shared__ float Ps[16][132];
    __shared__ float Vs[16][68];
    const int tid = threadIdx.x;
    const int bh  = blockIdx.y;
    const int b   = bh >> 4, h = bh & 15;
    const float* pb = P + (size_t)bh * SLEN * SLEN;
    const float* vbse = V + b*DMODEL + h*HDIM;
    const int bm = blockIdx.x * 128;
    const int ty = tid >> 4, tx = tid & 15;

    const int prow = tid >> 2;            // 0..63
    const int pseg = (tid & 3) * 4;       // 0,4,8,12
    const int vrow = tid >> 4;            // 0..15
    const int vseg = (tid & 15) * 4;      // 0..60

    float acc[8][4];
#pragma unroll
    for (int i = 0; i < 8; i++)
#pragma unroll
        for (int j = 0; j < 4; j++) acc[i][j] = 0.f;

    float4 p0 = *(const float4*)(pb + (size_t)(bm+prow)    * SLEN + pseg);
    float4 p1 = *(const float4*)(pb + (size_t)(bm+prow+64) * SLEN + pseg);
    float4 vv = *(const float4*)(vbse + (size_t)vrow * LDAQ + vseg);

    for (int k0 = 0; k0 < SLEN; k0 += 16) {
        Ps[pseg+0][prow] = p0.x; Ps[pseg+1][prow] = p0.y;
        Ps[pseg+2][prow] = p0.z; Ps[pseg+3][prow] = p0.w;
        Ps[pseg+0][prow+64] = p1.x; Ps[pseg+1][prow+64] = p1.y;
        Ps[pseg+2][prow+64] = p1.z; Ps[pseg+3][prow+64] = p1.w;
        *(float4*)&Vs[vrow][vseg] = vv;
        __syncthreads();
        if (k0 + 16 < SLEN) {
            p0 = *(const float4*)(pb + (size_t)(bm+prow)    * SLEN + k0 + 16 + pseg);
            p1 = *(const float4*)(pb + (size_t)(bm+prow+64) * SLEN + k0 + 16 + pseg);
            vv = *(const float4*)(vbse + (size_t)(k0 + 16 + vrow) * LDAQ + vseg);
        }
#pragma unroll
        for (int kk = 0; kk < 16; kk++) {
            float4 a0 = *(const float4*)&Ps[kk][ty*8];
            float4 a1 = *(const float4*)&Ps[kk][ty*8+4];
            float4 bv = *(const float4*)&Vs[kk][tx*4];
            float a[8] = {a0.x,a0.y,a0.z,a0.w,a1.x,a1.y,a1.z,a1.w};
            float bb[4]= {bv.x,bv.y,bv.z,bv.w};
#pragma unroll
            for (int i = 0; i < 8; i++)
#pragma unroll
                for (int j = 0; j < 4; j++) acc[i][j] += a[i]*bb[j];
        }
        __syncthreads();
    }

#pragma unroll
    for (int i = 0; i < 8; i++) {
        const int s = bm + ty*8 + i;
        float* op = O + ((size_t)s * BATCH + b) * DMODEL + h*HDIM + tx*4;
        *(float4*)op = make_float4(acc[i][0],acc[i][1],acc[i][2],acc[i][3]);
    }
}

// ---------------------------------------------------------------------------
// out[r,:] = LayerNorm(y[r,:] + res[r,:]) * g + b.  One block per row, D=1024.
// ---------------------------------------------------------------------------
__global__ void add_ln(const float* __restrict__ y, const float* __restrict__ res,
                       const float* __restrict__ g, const float* __restrict__ be,
                       float* __restrict__ out)
{
    const int r   = blockIdx.x;
    const int tid = threadIdx.x;
    const float4 a  = ((const float4*)(y   + (size_t)r*DMODEL))[tid];
    const float4 b4 = ((const float4*)(res + (size_t)r*DMODEL))[tid];
    float x0 = a.x + b4.x, x1 = a.y + b4.y, x2 = a.z + b4.z, x3 = a.w + b4.w;
    float s = x0 + x1 + x2 + x3;
    float q = x0*x0 + x1*x1 + x2*x2 + x3*x3;

    __shared__ float rs[8], rq[8];
#pragma unroll
    for (int o = 16; o; o >>= 1) {
        s += __shfl_xor_sync(0xffffffffu, s, o);
        q += __shfl_xor_sync(0xffffffffu, q, o);
    }
    if ((tid & 31) == 0) { rs[tid >> 5] = s; rq[tid >> 5] = q; }
    __syncthreads();
    float st = 0.f, qt = 0.f;
#pragma unroll
    for (int i = 0; i < 8; i++) { st += rs[i]; qt += rq[i]; }
    const float mean = st * (1.f/1024.f);
    const float var  = qt * (1.f/1024.f) - mean*mean;
    const float rstd = rsqrtf(var + 1e-5f);

    const float4 gv = ((const float4*)g)[tid];
    const float4 bv = ((const float4*)be)[tid];
    float4 o;
    o.x = (x0 - mean) * rstd * gv.x + bv.x;
    o.y = (x1 - mean) * rstd * gv.y + bv.y;
    o.z = (x2 - mean) * rstd * gv.z + bv.z;
    o.w = (x3 - mean) * rstd * gv.w + bv.w;
    ((float4*)(out + (size_t)r*DMODEL))[tid] = o;
}

// ---------------------------------------------------------------------------
extern "C" void kernel_launch(void* const* d_in, const int* in_sizes, int n_in,
                              void* d_out, int out_size)
{
    const float* state = (const float*)d_in[0];
    const void*  mask  = d_in[1];
    const float* Wq = (const float*)d_in[2];  const float* bq = (const float*)d_in[3];
    const float* Wk = (const float*)d_in[4];  const float* bk = (const float*)d_in[5];
    const float* Wv = (const float*)d_in[6];  const float* bv = (const float*)d_in[7];
    const float* Wo = (const float*)d_in[8];  const float* bo = (const float*)d_in[9];
    const float* g1 = (const float*)d_in[10]; const float* be1 = (const float*)d_in[11];
    const float* W1 = (const float*)d_in[12]; const float* b1 = (const float*)d_in[13];
    const float* W2 = (const float*)d_in[14]; const float* b2 = (const float*)d_in[15];
    const float* g2 = (const float*)d_in[16]; const float* be2 = (const float*)d_in[17];
    float* out = (float*)d_out;

    float *q, *k, *v, *att, *y, *x1, *h, *y2, *p;
    cudaGetSymbolAddress((void**)&q,   g_q);
    cudaGetSymbolAddress((void**)&k,   g_k);
    cudaGetSymbolAddress((void**)&v,   g_v);
    cudaGetSymbolAddress((void**)&att, g_att);
    cudaGetSymbolAddress((void**)&y,   g_y);
    cudaGetSymbolAddress((void**)&x1,  g_x1);
    cudaGetSymbolAddress((void**)&h,   g_h);
    cudaGetSymbolAddress((void**)&y2,  g_y2);
    cudaGetSymbolAddress((void**)&p,   g_p);

    const dim3 thr(256);
    // QKV projections
    gemm_nt<false><<<dim3(DMODEL/128, NROW/128), thr>>>(state, Wq, bq, q, NROW, DMODEL, DMODEL);
    gemm_nt<false><<<dim3(DMODEL/128, NROW/128), thr>>>(state, Wk, bk, k, NROW, DMODEL, DMODEL);
    gemm_nt<false><<<dim3(DMODEL/128, NROW/128), thr>>>(state, Wv, bv, v, NROW, DMODEL, DMODEL);
    // attention
    attn_scores<<<dim3(SLEN/128, SLEN/128, BATCH*NHEAD), thr>>>(q, k, p);
    softmax_mask<<<dim3(SLEN, BATCH*NHEAD), thr>>>(p, mask);
    attn_pv<<<dim3(SLEN/128, BATCH*NHEAD), thr>>>(p, v, att);
    // output projection + LN1
    gemm_nt<false><<<dim3(DMODEL/128, NROW/128), thr>>>(att, Wo, bo, y, NROW, DMODEL, DMODEL);
    add_ln<<<NROW, 256>>>(y, state, g1, be1, x1);
    // FFN + LN2
    gemm_nt<true ><<<dim3(FFDIM/128, NROW/128), thr>>>(x1, W1, b1, h, NROW, FFDIM, DMODEL);
    gemm_nt<false><<<dim3(DMODEL/128, NROW/128), thr>>>(h, W2, b2, y2, NROW, DMODEL, FFDIM);
    add_ln<<<NROW, 256>>>(y2, x1, g2, be2, out);
}

// round 2
// speedup vs baseline: 2.1912x; 2.1912x over previous
#include <cuda_runtime.h>
#include <math.h>

#define SLEN 2048
#define BATCH 4
#define DMODEL 1024
#define NHEAD 16
#define HDIM 64
#define FFDIM 4096
#define NROW (SLEN*BATCH)      /* 8192 */
#define LDAQ (BATCH*DMODEL)    /* 4096 */

// ------------------------- static scratch -----------------------------------
__device__ float g_q  [NROW*DMODEL];
__device__ float g_k  [NROW*DMODEL];
__device__ float g_v  [NROW*DMODEL];
__device__ float g_att[NROW*DMODEL];
__device__ float g_y  [NROW*DMODEL];
__device__ float g_x1 [NROW*DMODEL];
__device__ float g_h  [NROW*FFDIM];
__device__ float g_y2 [NROW*DMODEL];
__device__ float g_p  [268435456];   // [B*H, S, S]

// --------------------------- tf32 helpers -----------------------------------
__device__ __forceinline__ unsigned f2t(float f) {
    unsigned u; asm("cvt.rna.tf32.f32 %0, %1;" : "=r"(u) : "f"(f)); return u;
}
__device__ __forceinline__ void st4(unsigned* p, float4 v) {
    p[0] = f2t(v.x); p[1] = f2t(v.y); p[2] = f2t(v.z); p[3] = f2t(v.w);
}
__device__ __forceinline__ void mma8(float* c, const unsigned* a, unsigned b0, unsigned b1) {
    asm("mma.sync.aligned.m16n8k8.row.col.f32.tf32.tf32.f32 "
        "{%0,%1,%2,%3},{%4,%5,%6,%7},{%8,%9},{%0,%1,%2,%3};"
        : "+f"(c[0]), "+f"(c[1]), "+f"(c[2]), "+f"(c[3])
        : "r"(a[0]), "r"(a[1]), "r"(a[2]), "r"(a[3]), "r"(b0), "r"(b1));
}

// ---------------------------------------------------------------------------
// Dense GEMM:  C[M,N] = A[M,K] * W[N,K]^T + bias  (opt ReLU)
// 128x128x16 tiles, 256 thr, warp 64x32 via mma.m16n8k8.tf32
// ---------------------------------------------------------------------------
template<bool RELU>
__global__ __launch_bounds__(256, 2)
void gemm_mma_nt(const float* __restrict__ A, const float* __restrict__ W,
                 const float* __restrict__ bias, float* __restrict__ C,
                 int N, int K)
{
    __shared__ unsigned As[128*20];
    __shared__ unsigned Bs[128*20];
    const int tid  = threadIdx.x;
    const int lane = tid & 31, wid = tid >> 5;
    const int wm = wid >> 2, wn = wid & 3;        // 2 x 4 warp grid
    const int grp = lane >> 2, qd = lane & 3;
    const int bm = blockIdx.y * 128, bn = blockIdx.x * 128;

    const int r0 = tid >> 2,        s0 = (tid & 3) * 4;        // load slot 0
    const int r1 = (tid + 256) >> 2, s1 = s0;                  // load slot 1 (rows 64..127)

    const float* A0 = A + (size_t)(bm + r0) * K + s0;
    const float* A1 = A + (size_t)(bm + r1) * K + s1;
    const float* W0 = W + (size_t)(bn + r0) * K + s0;
    const float* W1p= W + (size_t)(bn + r1) * K + s1;

    float acc[4][4][4];
#pragma unroll
    for (int i = 0; i < 4; i++)
#pragma unroll
        for (int j = 0; j < 4; j++)
#pragma unroll
            for (int x = 0; x < 4; x++) acc[i][j][x] = 0.f;

    float4 av0 = *(const float4*)A0, av1 = *(const float4*)A1;
    float4 bv0 = *(const float4*)W0, bv1 = *(const float4*)W1p;

    for (int k0 = 0; k0 < K; k0 += 16) {
        st4(&As[r0*20 + s0], av0); st4(&As[r1*20 + s1], av1);
        st4(&Bs[r0*20 + s0], bv0); st4(&Bs[r1*20 + s1], bv1);
        __syncthreads();
        if (k0 + 16 < K) {
            av0 = *(const float4*)(A0 + k0 + 16); av1 = *(const float4*)(A1 + k0 + 16);
            bv0 = *(const float4*)(W0 + k0 + 16); bv1 = *(const float4*)(W1p + k0 + 16);
        }
#pragma unroll
        for (int k8 = 0; k8 < 16; k8 += 8) {
            unsigned a[4][4], b[4][2];
#pragma unroll
            for (int mi = 0; mi < 4; mi++) {
                const int r = wm*64 + mi*16 + grp;
                a[mi][0] = As[r*20 + k8 + qd];
                a[mi][1] = As[(r+8)*20 + k8 + qd];
                a[mi][2] = As[r*20 + k8 + qd + 4];
                a[mi][3] = As[(r+8)*20 + k8 + qd + 4];
            }
#pragma unroll
            for (int ni = 0; ni < 4; ni++) {
                const int n = wn*32 + ni*8 + grp;
                b[ni][0] = Bs[n*20 + k8 + qd];
                b[ni][1] = Bs[n*20 + k8 + qd + 4];
            }
#pragma unroll
            for (int mi = 0; mi < 4; mi++)
#pragma unroll
                for (int ni = 0; ni < 4; ni++)
                    mma8(acc[mi][ni], a[mi], b[ni][0], b[ni][1]);
        }
        __syncthreads();
    }

#pragma unroll
    for (int mi = 0; mi < 4; mi++) {
        const int row = bm + wm*64 + mi*16 + grp;
#pragma unroll
        for (int ni = 0; ni < 4; ni++) {
            const int col = bn + wn*32 + ni*8 + qd*2;
            float g0 = bias[col], g1 = bias[col+1];
            float o0 = acc[mi][ni][0] + g0, o1 = acc[mi][ni][1] + g1;
            float o2 = acc[mi][ni][2] + g0, o3 = acc[mi][ni][3] + g1;
            if (RELU) { o0=fmaxf(o0,0.f); o1=fmaxf(o1,0.f); o2=fmaxf(o2,0.f); o3=fmaxf(o3,0.f); }
            *(float2*)(C + (size_t)row    * N + col) = make_float2(o0, o1);
            *(float2*)(C + (size_t)(row+8)* N + col) = make_float2(o2, o3);
        }
    }
}

// ---------------------------------------------------------------------------
// Scores: P[bh][s][t] = sum_d q(s,b,h,d) * k(t,b,h,d)   (raw; scale in softmax)
// ---------------------------------------------------------------------------
__global__ __launch_bounds__(256, 2)
void score_mma(const float* __restrict__ Q, const float* __restrict__ Km,
               float* __restrict__ P)
{
    __shared__ unsigned As[128*20];
    __shared__ unsigned Bs[128*20];
    const int tid  = threadIdx.x;
    const int lane = tid & 31, wid = tid >> 5;
    const int wm = wid >> 2, wn = wid & 3;
    const int grp = lane >> 2, qd = lane & 3;
    const int bh = blockIdx.z, b = bh >> 4, h = bh & 15;
    const int bm = blockIdx.y * 128, bn = blockIdx.x * 128;

    const float* qb = Q  + b*DMODEL + h*HDIM;
    const float* kb = Km + b*DMODEL + h*HDIM;

    const int r0 = tid >> 2,        s0 = (tid & 3) * 4;
    const int r1 = (tid + 256) >> 2;

    float acc[4][4][4];
#pragma unroll
    for (int i = 0; i < 4; i++)
#pragma unroll
        for (int j = 0; j < 4; j++)
#pragma unroll
            for (int x = 0; x < 4; x++) acc[i][j][x] = 0.f;

    float4 av0 = *(const float4*)(qb + (size_t)(bm+r0)*LDAQ + s0);
    float4 av1 = *(const float4*)(qb + (size_t)(bm+r1)*LDAQ + s0);
    float4 bv0 = *(const float4*)(kb + (size_t)(bn+r0)*LDAQ + s0);
    float4 bv1 = *(const float4*)(kb + (size_t)(bn+r1)*LDAQ + s0);

    for (int k0 = 0; k0 < HDIM; k0 += 16) {
        st4(&As[r0*20 + s0], av0); st4(&As[r1*20 + s0], av1);
        st4(&Bs[r0*20 + s0], bv0); st4(&Bs[r1*20 + s0], bv1);
        __syncthreads();
        if (k0 + 16 < HDIM) {
            av0 = *(const float4*)(qb + (size_t)(bm+r0)*LDAQ + k0 + 16 + s0);
            av1 = *(const float4*)(qb + (size_t)(bm+r1)*LDAQ + k0 + 16 + s0);
            bv0 = *(const float4*)(kb + (size_t)(bn+r0)*LDAQ + k0 + 16 + s0);
            bv1 = *(const float4*)(kb + (size_t)(bn+r1)*LDAQ + k0 + 16 + s0);
        }
#pragma unroll
        for (int k8 = 0; k8 < 16; k8 += 8) {
            unsigned a[4][4], b2[4][2];
#pragma unroll
            for (int mi = 0; mi < 4; mi++) {
                const int r = wm*64 + mi*16 + grp;
                a[mi][0] = As[r*20 + k8 + qd];
                a[mi][1] = As[(r+8)*20 + k8 + qd];
                a[mi][2] = As[r*20 + k8 + qd + 4];
                a[mi][3] = As[(r+8)*20 + k8 + qd + 4];
            }
#pragma unroll
            for (int ni = 0; ni < 4; ni++) {
                const int n = wn*32 + ni*8 + grp;
                b2[ni][0] = Bs[n*20 + k8 + qd];
                b2[ni][1] = Bs[n*20 + k8 + qd + 4];
            }
#pragma unroll
            for (int mi = 0; mi < 4; mi++)
#pragma unroll
                for (int ni = 0; ni < 4; ni++)
                    mma8(acc[mi][ni], a[mi], b2[ni][0], b2[ni][1]);
        }
        __syncthreads();
    }

    float* pp = P + (size_t)bh * SLEN * SLEN;
#pragma unroll
    for (int mi = 0; mi < 4; mi++) {
        const int row = bm + wm*64 + mi*16 + grp;
#pragma unroll
        for (int ni = 0; ni < 4; ni++) {
            const int col = bn + wn*32 + ni*8 + qd*2;
            *(float2*)(pp + (size_t)row    * SLEN + col) = make_float2(acc[mi][ni][0], acc[mi][ni][1]);
            *(float2*)(pp + (size_t)(row+8)* SLEN + col) = make_float2(acc[mi][ni][2], acc[mi][ni][3]);
        }
    }
}

// ---------------------------------------------------------------------------
// PV: O[s,d] = sum_t P[s,t] * v(t,b,h,d).  128x64x16 tiles, warp 32x32.
// ---------------------------------------------------------------------------
__global__ __launch_bounds__(256, 2)
void pv_mma(const float* __restrict__ P, const float* __restrict__ V,
            float* __restrict__ O)
{
    __shared__ unsigned As[128*20];
    __shared__ unsigned Bs[16*72];
    const int tid  = threadIdx.x;
    const int lane = tid & 31, wid = tid >> 5;
    const int wm = wid >> 1, wn = wid & 1;        // 4 x 2 warp grid, 32x32 tiles
    const int grp = lane >> 2, qd = lane & 3;
    const int bh = blockIdx.y, b = bh >> 4, h = bh & 15;
    const int bm = blockIdx.x * 128;

    const float* pb = P + (size_t)bh * SLEN * SLEN;
    const float* vb = V + b*DMODEL + h*HDIM;

    const int r0 = tid >> 2,        s0 = (tid & 3) * 4;
    const int r1 = (tid + 256) >> 2;
    const int trow = tid >> 4, dcol = (tid & 15) * 4;

    float acc[2][4][4];
#pragma unroll
    for (int i = 0; i < 2; i++)
#pragma unroll
        for (int j = 0; j < 4; j++)
#pragma unroll
            for (int x = 0; x < 4; x++) acc[i][j][x] = 0.f;

    float4 av0 = *(const float4*)(pb + (size_t)(bm+r0)*SLEN + s0);
    float4 av1 = *(const float4*)(pb + (size_t)(bm+r1)*SLEN + s0);
    float4 vv  = *(const float4*)(vb + (size_t)trow * LDAQ + dcol);

    for (int k0 = 0; k0 < SLEN; k0 += 16) {
        st4(&As[r0*20 + s0], av0); st4(&As[r1*20 + s0], av1);
        st4(&Bs[trow*72 + dcol], vv);
        __syncthreads();
        if (k0 + 16 < SLEN) {
            av0 = *(const float4*)(pb + (size_t)(bm+r0)*SLEN + k0 + 16 + s0);
            av1 = *(const float4*)(pb + (size_t)(bm+r1)*SLEN + k0 + 16 + s0);
            vv  = *(const float4*)(vb + (size_t)(k0 + 16 + trow) * LDAQ + dcol);
        }
#pragma unroll
        for (int k8 = 0; k8 < 16; k8 += 8) {
            unsigned a[2][4], b2[4][2];
#pragma unroll
            for (int mi = 0; mi < 2; mi++) {
                const int r = wm*32 + mi*16 + grp;
                a[mi][0] = As[r*20 + k8 + qd];
                a[mi][1] = As[(r+8)*20 + k8 + qd];
                a[mi][2] = As[r*20 + k8 + qd + 4];
                a[mi][3] = As[(r+8)*20 + k8 + qd + 4];
            }
#pragma unroll
            for (int ni = 0; ni < 4; ni++) {
                const int n = wn*32 + ni*8 + grp;
                b2[ni][0] = Bs[(k8 + qd)*72 + n];
                b2[ni][1] = Bs[(k8 + qd + 4)*72 + n];
            }
#pragma unroll
            for (int mi = 0; mi < 2; mi++)
#pragma unroll
                for (int ni = 0; ni < 4; ni++)
                    mma8(acc[mi][ni], a[mi], b2[ni][0], b2[ni][1]);
        }
        __syncthreads();
    }

#pragma unroll
    for (int mi = 0; mi < 2; mi++) {
        const int s = bm + wm*32 + mi*16 + grp;
#pragma unroll
        for (int ni = 0; ni < 4; ni++) {
            const int col = wn*32 + ni*8 + qd*2;
            float* o0 = O + ((size_t)s    * BATCH + b) * DMODEL + h*HDIM + col;
            float* o1 = O + ((size_t)(s+8)* BATCH + b) * DMODEL + h*HDIM + col;
            *(float2*)o0 = make_float2(acc[mi][ni][0], acc[mi][ni][1]);
            *(float2*)o1 = make_float2(acc[mi][ni][2], acc[mi][ni][3]);
        }
    }
}

// ---------------------------------------------------------------------------
// Masked softmax over key dim, in place (mask dtype probed at runtime).
// ---------------------------------------------------------------------------
__global__ void softmax_mask(float* __restrict__ P, const void* __restrict__ mask)
{
    const int bh  = blockIdx.y;
    const int b   = bh >> 4;
    const int row = blockIdx.x;
    float* p = P + (size_t)bh * SLEN * SLEN + (size_t)row * SLEN;

    const unsigned char* m8  = (const unsigned char*)mask;
    const int*           m32 = (const int*)mask;
    const bool isu8 = (m8[SLEN - 1] == 1);

    const int tid = threadIdx.x;
    float vals[8];
    float mx = -INFINITY;
#pragma unroll
    for (int i = 0; i < 8; i++) {
        const int t = tid + i * 256;
        const bool mk = isu8 ? (m8[b*SLEN + t] != 0) : (m32[b*SLEN + t] != 0);
        const float v = mk ? -INFINITY : p[t] * 0.125f;
        vals[i] = v;
        mx = fmaxf(mx, v);
    }

    __shared__ float red[8];
#pragma unroll
    for (int o = 16; o; o >>= 1) mx = fmaxf(mx, __shfl_xor_sync(0xffffffffu, mx, o));
    if ((tid & 31) == 0) red[tid >> 5] = mx;
    __syncthreads();
    float bmax = red[0];
#pragma unroll
    for (int i = 1; i < 8; i++) bmax = fmaxf(bmax, red[i]);
    __syncthreads();

    float ssum = 0.f;
#pragma unroll
    for (int i = 0; i < 8; i++) {
        vals[i] = __expf(vals[i] - bmax);
        ssum += vals[i];
    }
#pragma unroll
    for (int o = 16; o; o >>= 1) ssum += __shfl_xor_sync(0xffffffffu, ssum, o);
    if ((tid & 31) == 0) red[tid >> 5] = ssum;
    __syncthreads();
    float tot = 0.f;
#pragma unroll
    for (int i = 0; i < 8; i++) tot += red[i];
    const float inv = 1.f / tot;

#pragma unroll
    for (int i = 0; i < 8; i++) p[tid + i * 256] = vals[i] * inv;
}

// ---------------------------------------------------------------------------
// out = LayerNorm(y + res) * g + b, one block per row (D=1024)
// ---------------------------------------------------------------------------
__global__ void add_ln(const float* __restrict__ y, const float* __restrict__ res,
                       const float* __restrict__ g, const float* __restrict__ be,
                       float* __restrict__ out)
{
    const int r   = blockIdx.x;
    const int tid = threadIdx.x;
    const float4 a  = ((const float4*)(y   + (size_t)r*DMODEL))[tid];
    const float4 b4 = ((const float4*)(res + (size_t)r*DMODEL))[tid];
    float x0 = a.x + b4.x, x1 = a.y + b4.y, x2 = a.z + b4.z, x3 = a.w + b4.w;
    float s = x0 + x1 + x2 + x3;
    float q = x0*x0 + x1*x1 + x2*x2 + x3*x3;

    __shared__ float rs[8], rq[8];
#pragma unroll
    for (int o = 16; o; o >>= 1) {
        s += __shfl_xor_sync(0xffffffffu, s, o);
        q += __shfl_xor_sync(0xffffffffu, q, o);
    }
    if ((tid & 31) == 0) { rs[tid >> 5] = s; rq[tid >> 5] = q; }
    __syncthreads();
    float st = 0.f, qt = 0.f;
#pragma unroll
    for (int i = 0; i < 8; i++) { st += rs[i]; qt += rq[i]; }
    const float mean = st * (1.f/1024.f);
    const float var  = qt * (1.f/1024.f) - mean*mean;
    const float rstd = rsqrtf(var + 1e-5f);

    const float4 gv = ((const float4*)g)[tid];
    const float4 bv = ((const float4*)be)[tid];
    float4 o;
    o.x = (x0 - mean) * rstd * gv.x + bv.x;
    o.y = (x1 - mean) * rstd * gv.y + bv.y;
    o.z = (x2 - mean) * rstd * gv.z + bv.z;
    o.w = (x3 - mean) * rstd * gv.w + bv.w;
    ((float4*)(out + (size_t)r*DMODEL))[tid] = o;
}

// ---------------------------------------------------------------------------
extern "C" void kernel_launch(void* const* d_in, const int* in_sizes, int n_in,
                              void* d_out, int out_size)
{
    const float* state = (const float*)d_in[0];
    const void*  mask  = d_in[1];
    const float* Wq = (const float*)d_in[2];  const float* bq = (const float*)d_in[3];
    const float* Wk = (const float*)d_in[4];  const float* bk = (const float*)d_in[5];
    const float* Wv = (const float*)d_in[6];  const float* bv = (const float*)d_in[7];
    const float* Wo = (const float*)d_in[8];  const float* bo = (const float*)d_in[9];
    const float* g1 = (const float*)d_in[10]; const float* be1 = (const float*)d_in[11];
    const float* W1 = (const float*)d_in[12]; const float* b1 = (const float*)d_in[13];
    const float* W2 = (const float*)d_in[14]; const float* b2 = (const float*)d_in[15];
    const float* g2 = (const float*)d_in[16]; const float* be2 = (const float*)d_in[17];
    float* out = (float*)d_out;

    float *q, *k, *v, *att, *y, *x1, *h, *y2, *p;
    cudaGetSymbolAddress((void**)&q,   g_q);
    cudaGetSymbolAddress((void**)&k,   g_k);
    cudaGetSymbolAddress((void**)&v,   g_v);
    cudaGetSymbolAddress((void**)&att, g_att);
    cudaGetSymbolAddress((void**)&y,   g_y);
    cudaGetSymbolAddress((void**)&x1,  g_x1);
    cudaGetSymbolAddress((void**)&h,   g_h);
    cudaGetSymbolAddress((void**)&y2,  g_y2);
    cudaGetSymbolAddress((void**)&p,   g_p);

    const dim3 thr(256);
    // QKV projections (tf32 tensor core)
    gemm_mma_nt<false><<<dim3(DMODEL/128, NROW/128), thr>>>(state, Wq, bq, q, DMODEL, DMODEL);
    gemm_mma_nt<false><<<dim3(DMODEL/128, NROW/128), thr>>>(state, Wk, bk, k, DMODEL, DMODEL);
    gemm_mma_nt<false><<<dim3(DMODEL/128, NROW/128), thr>>>(state, Wv, bv, v, DMODEL, DMODEL);
    // attention
    score_mma<<<dim3(SLEN/128, SLEN/128, BATCH*NHEAD), thr>>>(q, k, p);
    softmax_mask<<<dim3(SLEN, BATCH*NHEAD), thr>>>(p, mask);
    pv_mma<<<dim3(SLEN/128, BATCH*NHEAD), thr>>>(p, v, att);
    // output projection + LN1
    gemm_mma_nt<false><<<dim3(DMODEL/128, NROW/128), thr>>>(att, Wo, bo, y, DMODEL, DMODEL);
    add_ln<<<NROW, 256>>>(y, state, g1, be1, x1);
    // FFN + LN2
    gemm_mma_nt<true ><<<dim3(FFDIM/128, NROW/128), thr>>>(x1, W1, b1, h, FFDIM, DMODEL);
    gemm_mma_nt<false><<<dim3(DMODEL/128, NROW/128), thr>>>(h, W2, b2, y2, DMODEL, FFDIM);
    add_ln<<<NROW, 256>>>(y2, x1, g2, be2, out);
}

// round 4
// speedup vs baseline: 2.7171x; 1.2400x over previous
#include <cuda_runtime.h>
#include <math.h>

#define SLEN 2048
#define BATCH 4
#define DMODEL 1024
#define NHEAD 16
#define HDIM 64
#define FFDIM 4096
#define NROW (SLEN*BATCH)      /* 8192 */
#define LDAQ (BATCH*DMODEL)    /* 4096 */

// ------------------------- static scratch -----------------------------------
__device__ float g_q  [NROW*DMODEL];
__device__ float g_k  [NROW*DMODEL];
__device__ float g_v  [NROW*DMODEL];
__device__ float g_att[NROW*DMODEL];
__device__ float g_y  [NROW*DMODEL];
__device__ float g_x1 [NROW*DMODEL];
__device__ float g_h  [NROW*FFDIM];
__device__ float g_y2 [NROW*DMODEL];

// --------------------------- tf32 helpers -----------------------------------
__device__ __forceinline__ unsigned f2t(float f) {
    unsigned u; asm("cvt.rna.tf32.f32 %0, %1;" : "=r"(u) : "f"(f)); return u;
}
__device__ __forceinline__ void mma8(float* c, const unsigned* a, unsigned b0, unsigned b1) {
    asm("mma.sync.aligned.m16n8k8.row.col.f32.tf32.tf32.f32 "
        "{%0,%1,%2,%3},{%4,%5,%6,%7},{%8,%9},{%0,%1,%2,%3};"
        : "+f"(c[0]), "+f"(c[1]), "+f"(c[2]), "+f"(c[3])
        : "r"(a[0]), "r"(a[1]), "r"(a[2]), "r"(a[3]), "r"(b0), "r"(b1));
}

// ---------------------------------------------------------------------------
// Dense GEMM:  C[M,N] = A[M,K] * W[N,K]^T + bias  (opt ReLU)
// 128x128x16 tiles, 2-stage smem double buffer, warp 64x32 mma tiles.
// ---------------------------------------------------------------------------
template<bool RELU>
__global__ __launch_bounds__(256, 2)
void gemm_mma_nt(const float* __restrict__ A, const float* __restrict__ W,
                 const float* __restrict__ bias, float* __restrict__ C,
                 int N, int K)
{
    __shared__ unsigned As[2][128*20];
    __shared__ unsigned Bs[2][128*20];
    const int tid  = threadIdx.x;
    const int lane = tid & 31, wid = tid >> 5;
    const int wm = wid >> 2, wn = wid & 3;        // 2 x 4 warp grid
    const int grp = lane >> 2, qd = lane & 3;
    const int bm = blockIdx.y * 128, bn = blockIdx.x * 128;

    const int r0 = tid >> 2,         s0 = (tid & 3) * 4;
    const int r1 = (tid + 256) >> 2;

    const float* A0 = A + (size_t)(bm + r0) * K + s0;
    const float* A1 = A + (size_t)(bm + r1) * K + s0;
    const float* W0 = W + (size_t)(bn + r0) * K + s0;
    const float* W1p= W + (size_t)(bn + r1) * K + s0;

    float acc[4][4][4];
#pragma unroll
    for (int i = 0; i < 4; i++)
#pragma unroll
        for (int j = 0; j < 4; j++)
#pragma unroll
            for (int x = 0; x < 4; x++) acc[i][j][x] = 0.f;

    // prologue: tile 0 -> stage 0
    {
        float4 av0 = *(const float4*)A0, av1 = *(const float4*)A1;
        float4 bv0 = *(const float4*)W0, bv1 = *(const float4*)W1p;
        unsigned* pa0 = &As[0][r0*20 + s0];
        pa0[0]=f2t(av0.x); pa0[1]=f2t(av0.y); pa0[2]=f2t(av0.z); pa0[3]=f2t(av0.w);
        unsigned* pa1 = &As[0][r1*20 + s0];
        pa1[0]=f2t(av1.x); pa1[1]=f2t(av1.y); pa1[2]=f2t(av1.z); pa1[3]=f2t(av1.w);
        unsigned* pb0 = &Bs[0][r0*20 + s0];
        pb0[0]=f2t(bv0.x); pb0[1]=f2t(bv0.y); pb0[2]=f2t(bv0.z); pb0[3]=f2t(bv0.w);
        unsigned* pb1 = &Bs[0][r1*20 + s0];
        pb1[0]=f2t(bv1.x); pb1[1]=f2t(bv1.y); pb1[2]=f2t(bv1.z); pb1[3]=f2t(bv1.w);
    }
    __syncthreads();

    int buf = 0;
    for (int k0 = 0; k0 < K; k0 += 16) {
        float4 av0, av1, bv0, bv1;
        const bool more = (k0 + 16 < K);
        if (more) {
            av0 = *(const float4*)(A0 + k0 + 16); av1 = *(const float4*)(A1 + k0 + 16);
            bv0 = *(const float4*)(W0 + k0 + 16); bv1 = *(const float4*)(W1p + k0 + 16);
        }
#pragma unroll
        for (int k8 = 0; k8 < 16; k8 += 8) {
            unsigned a[4][4], b[4][2];
#pragma unroll
            for (int mi = 0; mi < 4; mi++) {
                const int r = wm*64 + mi*16 + grp;
                a[mi][0] = As[buf][r*20 + k8 + qd];
                a[mi][1] = As[buf][(r+8)*20 + k8 + qd];
                a[mi][2] = As[buf][r*20 + k8 + qd + 4];
                a[mi][3] = As[buf][(r+8)*20 + k8 + qd + 4];
            }
#pragma unroll
            for (int ni = 0; ni < 4; ni++) {
                const int n = wn*32 + ni*8 + grp;
                b[ni][0] = Bs[buf][n*20 + k8 + qd];
                b[ni][1] = Bs[buf][n*20 + k8 + qd + 4];
            }
#pragma unroll
            for (int mi = 0; mi < 4; mi++)
#pragma unroll
                for (int ni = 0; ni < 4; ni++)
                    mma8(acc[mi][ni], a[mi], b[ni][0], b[ni][1]);
        }
        if (more) {
            const int nb = buf ^ 1;
            unsigned* pa0 = &As[nb][r0*20 + s0];
            pa0[0]=f2t(av0.x); pa0[1]=f2t(av0.y); pa0[2]=f2t(av0.z); pa0[3]=f2t(av0.w);
            unsigned* pa1 = &As[nb][r1*20 + s0];
            pa1[0]=f2t(av1.x); pa1[1]=f2t(av1.y); pa1[2]=f2t(av1.z); pa1[3]=f2t(av1.w);
            unsigned* pb0 = &Bs[nb][r0*20 + s0];
            pb0[0]=f2t(bv0.x); pb0[1]=f2t(bv0.y); pb0[2]=f2t(bv0.z); pb0[3]=f2t(bv0.w);
            unsigned* pb1 = &Bs[nb][r1*20 + s0];
            pb1[0]=f2t(bv1.x); pb1[1]=f2t(bv1.y); pb1[2]=f2t(bv1.z); pb1[3]=f2t(bv1.w);
        }
        buf ^= 1;
        __syncthreads();
    }

#pragma unroll
    for (int mi = 0; mi < 4; mi++) {
        const int row = bm + wm*64 + mi*16 + grp;
#pragma unroll
        for (int ni = 0; ni < 4; ni++) {
            const int col = bn + wn*32 + ni*8 + qd*2;
            float g0 = bias[col], g1 = bias[col+1];
            float o0 = acc[mi][ni][0] + g0, o1 = acc[mi][ni][1] + g1;
            float o2 = acc[mi][ni][2] + g0, o3 = acc[mi][ni][3] + g1;
            if (RELU) { o0=fmaxf(o0,0.f); o1=fmaxf(o1,0.f); o2=fmaxf(o2,0.f); o3=fmaxf(o3,0.f); }
            *(float2*)(C + (size_t)row    * N + col) = make_float2(o0, o1);
            *(float2*)(C + (size_t)(row+8)* N + col) = make_float2(o2, o3);
        }
    }
}

// ---------------------------------------------------------------------------
// Fused flash attention: per block = (128 q-rows, one (b,h)).
// Loop over 64-key tiles: S=QK^T (tf32 mma), mask, online softmax, O += P*V.
// smem (dynamic, ~107KB): Qs 128x68, Ks 64x68, Vs 64x72, Ps 128x68,
//                         redm/redl 2x128, mask 2048B.
// ---------------------------------------------------------------------------
__global__ __launch_bounds__(256, 1)
void flash_attn(const float* __restrict__ Q, const float* __restrict__ K,
                const float* __restrict__ V, const void* __restrict__ mask,
                float* __restrict__ O)
{
    extern __shared__ unsigned smem_u[];
    unsigned* Qs = smem_u;                 // 128*68
    unsigned* Ks = Qs + 128*68;            // 64*68
    unsigned* Vs = Ks + 64*68;             // 64*72
    unsigned* Ps = Vs + 64*72;             // 128*68
    float* redm = (float*)(Ps + 128*68);   // 256
    float* redl = redm + 256;              // 256
    unsigned char* msk = (unsigned char*)(redl + 256);  // 2048

    const int tid = threadIdx.x, lane = tid & 31, wid = tid >> 5;
    const int wm = wid >> 1, wn = wid & 1;       // 4 x 2 warps, 32x32 tiles
    const int grp = lane >> 2, qd = lane & 3;
    const int bh = blockIdx.y, b = bh >> 4, h = bh & 15;
    const int bm = blockIdx.x * 128;

    const float* qb = Q + b*DMODEL + h*HDIM;
    const float* kb = K + b*DMODEL + h*HDIM;
    const float* vb = V + b*DMODEL + h*HDIM;

    // mask row for this batch -> smem (handles u8-bool or int32 layouts)
    {
        const unsigned char* m8  = (const unsigned char*)mask;
        const int*           m32 = (const int*)mask;
        const bool isu8 = (m8[SLEN - 1] == 1);
        for (int t = tid; t < SLEN; t += 256)
            msk[t] = isu8 ? (m8[(size_t)b*SLEN + t] != 0)
                          : (m32[(size_t)b*SLEN + t] != 0);
    }
    // Q tile -> smem, pre-scaled by 1/sqrt(HD)=0.125
    {
        const int r = tid >> 4, c = (tid & 15) * 4;
#pragma unroll
        for (int p = 0; p < 8; p++) {
            const int rr = r + p*16;
            float4 v4 = *(const float4*)(qb + (size_t)(bm + rr) * LDAQ + c);
            unsigned* d = &Qs[rr*68 + c];
            d[0]=f2t(v4.x*0.125f); d[1]=f2t(v4.y*0.125f);
            d[2]=f2t(v4.z*0.125f); d[3]=f2t(v4.w*0.125f);
        }
    }

    float m_st[2][2], l_st[2][2];
    float oacc[2][4][4];
#pragma unroll
    for (int mi = 0; mi < 2; mi++) {
        m_st[mi][0] = -INFINITY; m_st[mi][1] = -INFINITY;
        l_st[mi][0] = 0.f;       l_st[mi][1] = 0.f;
#pragma unroll
        for (int ni = 0; ni < 4; ni++)
#pragma unroll
            for (int x = 0; x < 4; x++) oacc[mi][ni][x] = 0.f;
    }

    const int rkv = tid >> 4, ckv = (tid & 15) * 4;

    for (int kt = 0; kt < SLEN; kt += 64) {
        __syncthreads();   // prev-iter PV reads of Ks/Vs complete
        // K,V tile -> smem
#pragma unroll
        for (int p = 0; p < 4; p++) {
            const int rr = rkv + p*16;
            float4 k4 = *(const float4*)(kb + (size_t)(kt + rr) * LDAQ + ckv);
            float4 v4 = *(const float4*)(vb + (size_t)(kt + rr) * LDAQ + ckv);
            unsigned* dk = &Ks[rr*68 + ckv];
            dk[0]=f2t(k4.x); dk[1]=f2t(k4.y); dk[2]=f2t(k4.z); dk[3]=f2t(k4.w);
            unsigned* dv = &Vs[rr*72 + ckv];
            dv[0]=f2t(v4.x); dv[1]=f2t(v4.y); dv[2]=f2t(v4.z); dv[3]=f2t(v4.w);
        }
        __syncthreads();

        // S = Q * K^T  (32x32 per warp)
        float sacc[2][4][4];
#pragma unroll
        for (int mi = 0; mi < 2; mi++)
#pragma unroll
            for (int ni = 0; ni < 4; ni++)
#pragma unroll
                for (int x = 0; x < 4; x++) sacc[mi][ni][x] = 0.f;
#pragma unroll
        for (int k8 = 0; k8 < 64; k8 += 8) {
            unsigned a[2][4], bb[4][2];
#pragma unroll
            for (int mi = 0; mi < 2; mi++) {
                const int r = wm*32 + mi*16 + grp;
                a[mi][0] = Qs[r*68 + k8 + qd];
                a[mi][1] = Qs[(r+8)*68 + k8 + qd];
                a[mi][2] = Qs[r*68 + k8 + qd + 4];
                a[mi][3] = Qs[(r+8)*68 + k8 + qd + 4];
            }
#pragma unroll
            for (int ni = 0; ni < 4; ni++) {
                const int n = wn*32 + ni*8 + grp;
                bb[ni][0] = Ks[n*68 + k8 + qd];
                bb[ni][1] = Ks[n*68 + k8 + qd + 4];
            }
#pragma unroll
            for (int mi = 0; mi < 2; mi++)
#pragma unroll
                for (int ni = 0; ni < 4; ni++)
                    mma8(sacc[mi][ni], a[mi], bb[ni][0], bb[ni][1]);
        }
        // mask
#pragma unroll
        for (int ni = 0; ni < 4; ni++) {
            const int c0 = kt + wn*32 + ni*8 + qd*2;
            if (msk[c0]) {
                sacc[0][ni][0] = -INFINITY; sacc[0][ni][2] = -INFINITY;
                sacc[1][ni][0] = -INFINITY; sacc[1][ni][2] = -INFINITY;
            }
            if (msk[c0+1]) {
                sacc[0][ni][1] = -INFINITY; sacc[0][ni][3] = -INFINITY;
                sacc[1][ni][1] = -INFINITY; sacc[1][ni][3] = -INFINITY;
            }
        }
        // row max: qd-lane shuffle + 2-warp smem reduce
#pragma unroll
        for (int mi = 0; mi < 2; mi++)
#pragma unroll
            for (int hf = 0; hf < 2; hf++) {
                float mx = -INFINITY;
#pragma unroll
                for (int ni = 0; ni < 4; ni++)
                    mx = fmaxf(mx, fmaxf(sacc[mi][ni][hf*2], sacc[mi][ni][hf*2+1]));
                mx = fmaxf(mx, __shfl_xor_sync(0xffffffffu, mx, 1));
                mx = fmaxf(mx, __shfl_xor_sync(0xffffffffu, mx, 2));
                if (qd == 0) redm[wn*128 + wm*32 + mi*16 + hf*8 + grp] = mx;
            }
        __syncthreads();

        float sc[2][2];
#pragma unroll
        for (int mi = 0; mi < 2; mi++)
#pragma unroll
            for (int hf = 0; hf < 2; hf++) {
                const int row = wm*32 + mi*16 + hf*8 + grp;
                const float tm = fmaxf(redm[row], redm[128 + row]);
                const float mnew = fmaxf(m_st[mi][hf], tm);
                sc[mi][hf] = __expf(m_st[mi][hf] - mnew);   // 0 when m_st=-inf
                m_st[mi][hf] = mnew;
            }
        // exp + row sums + P->smem (tf32)
        float ls[2][2] = {{0.f,0.f},{0.f,0.f}};
#pragma unroll
        for (int mi = 0; mi < 2; mi++) {
            const int r = wm*32 + mi*16 + grp;
#pragma unroll
            for (int ni = 0; ni < 4; ni++) {
                const int c = wn*32 + ni*8 + qd*2;
                float p0 = __expf(sacc[mi][ni][0] - m_st[mi][0]);
                float p1 = __expf(sacc[mi][ni][1] - m_st[mi][0]);
                float p2 = __expf(sacc[mi][ni][2] - m_st[mi][1]);
                float p3 = __expf(sacc[mi][ni][3] - m_st[mi][1]);
                ls[mi][0] += p0 + p1;
                ls[mi][1] += p2 + p3;
                Ps[r*68 + c]     = f2t(p0); Ps[r*68 + c + 1]     = f2t(p1);
                Ps[(r+8)*68 + c] = f2t(p2); Ps[(r+8)*68 + c + 1] = f2t(p3);
            }
        }
#pragma unroll
        for (int mi = 0; mi < 2; mi++)
#pragma unroll
            for (int hf = 0; hf < 2; hf++) {
                float s = ls[mi][hf];
                s += __shfl_xor_sync(0xffffffffu, s, 1);
                s += __shfl_xor_sync(0xffffffffu, s, 2);
                if (qd == 0) redl[wn*128 + wm*32 + mi*16 + hf*8 + grp] = s;
            }
        __syncthreads();
#pragma unroll
        for (int mi = 0; mi < 2; mi++)
#pragma unroll
            for (int hf = 0; hf < 2; hf++) {
                const int row = wm*32 + mi*16 + hf*8 + grp;
                l_st[mi][hf] = l_st[mi][hf] * sc[mi][hf] + redl[row] + redl[128 + row];
            }
        // rescale O accumulators
#pragma unroll
        for (int mi = 0; mi < 2; mi++)
#pragma unroll
            for (int ni = 0; ni < 4; ni++) {
                oacc[mi][ni][0] *= sc[mi][0]; oacc[mi][ni][1] *= sc[mi][0];
                oacc[mi][ni][2] *= sc[mi][1]; oacc[mi][ni][3] *= sc[mi][1];
            }
        // O += P * V
#pragma unroll
        for (int k8 = 0; k8 < 64; k8 += 8) {
            unsigned a[2][4], bb[4][2];
#pragma unroll
            for (int mi = 0; mi < 2; mi++) {
                const int r = wm*32 + mi*16 + grp;
                a[mi][0] = Ps[r*68 + k8 + qd];
                a[mi][1] = Ps[(r+8)*68 + k8 + qd];
                a[mi][2] = Ps[r*68 + k8 + qd + 4];
                a[mi][3] = Ps[(r+8)*68 + k8 + qd + 4];
            }
#pragma unroll
            for (int ni = 0; ni < 4; ni++) {
                const int n = wn*32 + ni*8 + grp;
                bb[ni][0] = Vs[(k8 + qd)*72 + n];
                bb[ni][1] = Vs[(k8 + qd + 4)*72 + n];
            }
#pragma unroll
            for (int mi = 0; mi < 2; mi++)
#pragma unroll
                for (int ni = 0; ni < 4; ni++)
                    mma8(oacc[mi][ni], a[mi], bb[ni][0], bb[ni][1]);
        }
    }

    // epilogue: O /= l, write [s*B+b, h*64+d]
#pragma unroll
    for (int mi = 0; mi < 2; mi++) {
        const int s0 = bm + wm*32 + mi*16 + grp;
        const float inv0 = 1.f / l_st[mi][0];
        const float inv1 = 1.f / l_st[mi][1];
#pragma unroll
        for (int ni = 0; ni < 4; ni++) {
            const int c = h*HDIM + wn*32 + ni*8 + qd*2;
            float* o0 = O + ((size_t)s0     * BATCH + b) * DMODEL + c;
            float* o1 = O + ((size_t)(s0+8) * BATCH + b) * DMODEL + c;
            *(float2*)o0 = make_float2(oacc[mi][ni][0]*inv0, oacc[mi][ni][1]*inv0);
            *(float2*)o1 = make_float2(oacc[mi][ni][2]*inv1, oacc[mi][ni][3]*inv1);
        }
    }
}

// ---------------------------------------------------------------------------
// out = LayerNorm(y + res) * g + b, one block per row (D=1024)
// ---------------------------------------------------------------------------
__global__ void add_ln(const float* __restrict__ y, const float* __restrict__ res,
                       const float* __restrict__ g, const float* __restrict__ be,
                       float* __restrict__ out)
{
    const int r   = blockIdx.x;
    const int tid = threadIdx.x;
    const float4 a  = ((const float4*)(y   + (size_t)r*DMODEL))[tid];
    const float4 b4 = ((const float4*)(res + (size_t)r*DMODEL))[tid];
    float x0 = a.x + b4.x, x1 = a.y + b4.y, x2 = a.z + b4.z, x3 = a.w + b4.w;
    float s = x0 + x1 + x2 + x3;
    float q = x0*x0 + x1*x1 + x2*x2 + x3*x3;

    __shared__ float rs[8], rq[8];
#pragma unroll
    for (int o = 16; o; o >>= 1) {
        s += __shfl_xor_sync(0xffffffffu, s, o);
        q += __shfl_xor_sync(0xffffffffu, q, o);
    }
    if ((tid & 31) == 0) { rs[tid >> 5] = s; rq[tid >> 5] = q; }
    __syncthreads();
    float st = 0.f, qt = 0.f;
#pragma unroll
    for (int i = 0; i < 8; i++) { st += rs[i]; qt += rq[i]; }
    const float mean = st * (1.f/1024.f);
    const float var  = qt * (1.f/1024.f) - mean*mean;
    const float rstd = rsqrtf(var + 1e-5f);

    const float4 gv = ((const float4*)g)[tid];
    const float4 bv = ((const float4*)be)[tid];
    float4 o;
    o.x = (x0 - mean) * rstd * gv.x + bv.x;
    o.y = (x1 - mean) * rstd * gv.y + bv.y;
    o.z = (x2 - mean) * rstd * gv.z + bv.z;
    o.w = (x3 - mean) * rstd * gv.w + bv.w;
    ((float4*)(out + (size_t)r*DMODEL))[tid] = o;
}

// ---------------------------------------------------------------------------
#define FLASH_SMEM ((128*68 + 64*68 + 64*72 + 128*68) * 4 + 256*4*2 + 2048)

extern "C" void kernel_launch(void* const* d_in, const int* in_sizes, int n_in,
                              void* d_out, int out_size)
{
    const float* state = (const float*)d_in[0];
    const void*  mask  = d_in[1];
    const float* Wq = (const float*)d_in[2];  const float* bq = (const float*)d_in[3];
    const float* Wk = (const float*)d_in[4];  const float* bk = (const float*)d_in[5];
    const float* Wv = (const float*)d_in[6];  const float* bv = (const float*)d_in[7];
    const float* Wo = (const float*)d_in[8];  const float* bo = (const float*)d_in[9];
    const float* g1 = (const float*)d_in[10]; const float* be1 = (const float*)d_in[11];
    const float* W1 = (const float*)d_in[12]; const float* b1 = (const float*)d_in[13];
    const float* W2 = (const float*)d_in[14]; const float* b2 = (const float*)d_in[15];
    const float* g2 = (const float*)d_in[16]; const float* be2 = (const float*)d_in[17];
    float* out = (float*)d_out;

    float *q, *k, *v, *att, *y, *x1, *h, *y2;
    cudaGetSymbolAddress((void**)&q,   g_q);
    cudaGetSymbolAddress((void**)&k,   g_k);
    cudaGetSymbolAddress((void**)&v,   g_v);
    cudaGetSymbolAddress((void**)&att, g_att);
    cudaGetSymbolAddress((void**)&y,   g_y);
    cudaGetSymbolAddress((void**)&x1,  g_x1);
    cudaGetSymbolAddress((void**)&h,   g_h);
    cudaGetSymbolAddress((void**)&y2,  g_y2);

    cudaFuncSetAttribute(flash_attn, cudaFuncAttributeMaxDynamicSharedMemorySize,
                         FLASH_SMEM);

    const dim3 thr(256);
    // QKV projections
    gemm_mma_nt<false><<<dim3(DMODEL/128, NROW/128), thr>>>(state, Wq, bq, q, DMODEL, DMODEL);
    gemm_mma_nt<false><<<dim3(DMODEL/128, NROW/128), thr>>>(state, Wk, bk, k, DMODEL, DMODEL);
    gemm_mma_nt<false><<<dim3(DMODEL/128, NROW/128), thr>>>(state, Wv, bv, v, DMODEL, DMODEL);
    // fused attention
    flash_attn<<<dim3(SLEN/128, BATCH*NHEAD), thr, FLASH_SMEM>>>(q, k, v, mask, att);
    // output projection + LN1
    gemm_mma_nt<false><<<dim3(DMODEL/128, NROW/128), thr>>>(att, Wo, bo, y, DMODEL, DMODEL);
    add_ln<<<NROW, 256>>>(y, state, g1, be1, x1);
    // FFN + LN2
    gemm_mma_nt<true ><<<dim3(FFDIM/128, NROW/128), thr>>>(x1, W1, b1, h, FFDIM, DMODEL);
    gemm_mma_nt<false><<<dim3(DMODEL/128, NROW/128), thr>>>(h, W2, b2, y2, DMODEL, FFDIM);
    add_ln<<<NROW, 256>>>(y2, x1, g2, be2, out);
}

// round 6
// speedup vs baseline: 2.9274x; 1.0774x over previous
#include <cuda_runtime.h>
#include <math.h>

#define SLEN 2048
#define BATCH 4
#define DMODEL 1024
#define NHEAD 16
#define HDIM 64
#define FFDIM 4096
#define NROW (SLEN*BATCH)      /* 8192 */
#define LDAQ (BATCH*DMODEL)    /* 4096 */

// ------------------------- static scratch -----------------------------------
__device__ unsigned g_state_t[NROW*DMODEL];
__device__ unsigned g_wq_t[DMODEL*DMODEL];
__device__ unsigned g_wk_t[DMODEL*DMODEL];
__device__ unsigned g_wv_t[DMODEL*DMODEL];
__device__ unsigned g_wo_t[DMODEL*DMODEL];
__device__ unsigned g_w1_t[FFDIM*DMODEL];
__device__ unsigned g_w2_t[DMODEL*FFDIM];
__device__ float    g_q  [NROW*DMODEL];
__device__ float    g_k  [NROW*DMODEL];
__device__ float    g_v  [NROW*DMODEL];
__device__ unsigned g_att_t[NROW*DMODEL];
__device__ float    g_y  [NROW*DMODEL];
__device__ float    g_x1 [NROW*DMODEL];
__device__ unsigned g_x1_t[NROW*DMODEL];
__device__ unsigned g_h_t[NROW*FFDIM];
__device__ float    g_y2 [NROW*DMODEL];

// --------------------------- helpers ----------------------------------------
__device__ __forceinline__ unsigned f2t(float f) {
    unsigned u; asm("cvt.rna.tf32.f32 %0, %1;" : "=r"(u) : "f"(f)); return u;
}
__device__ __forceinline__ void mma8(float* c, const unsigned* a, unsigned b0, unsigned b1) {
    asm("mma.sync.aligned.m16n8k8.row.col.f32.tf32.tf32.f32 "
        "{%0,%1,%2,%3},{%4,%5,%6,%7},{%8,%9},{%0,%1,%2,%3};"
        : "+f"(c[0]), "+f"(c[1]), "+f"(c[2]), "+f"(c[3])
        : "r"(a[0]), "r"(a[1]), "r"(a[2]), "r"(a[3]), "r"(b0), "r"(b1));
}
__device__ __forceinline__ void cp16(unsigned dst, const void* src) {
    asm volatile("cp.async.ca.shared.global [%0], [%1], 16;" :: "r"(dst), "l"(src));
}

// fp32 -> tf32 bulk convert (n divisible by 4)
__global__ void f2t_kernel(const float* __restrict__ in, unsigned* __restrict__ out, int n4)
{
    int i = blockIdx.x * blockDim.x + threadIdx.x;
    if (i < n4) {
        float4 v = ((const float4*)in)[i];
        uint4 o = make_uint4(f2t(v.x), f2t(v.y), f2t(v.z), f2t(v.w));
        ((uint4*)out)[i] = o;
    }
}

// ---------------------------------------------------------------------------
// Dense GEMM on pre-converted tf32:  C[M,N] = A[M,K] * W[N,K]^T + bias
// 128x128x16 tiles, 4-stage cp.async pipeline (dynamic smem, 80KB),
// warp 64x32 mma tiles. OUT_T32: epilogue ReLU + tf32 store; else fp32.
// ---------------------------------------------------------------------------
#define GEMM_SLOT (128*20)                 /* u32 per stage per operand */
#define GEMM_SMEM (4*GEMM_SLOT*2*4)        /* bytes: 4 stages x (A+B) */

template<bool OUT_T32>
__global__ __launch_bounds__(256, 2)
void gemm_tt(const unsigned* __restrict__ A, const unsigned* __restrict__ W,
             const float* __restrict__ bias, void* __restrict__ Cout,
             int N, int K)
{
    extern __shared__ unsigned gs[];
    unsigned* As = gs;                      // 4 * GEMM_SLOT
    unsigned* Bs = gs + 4*GEMM_SLOT;        // 4 * GEMM_SLOT
    const int tid  = threadIdx.x;
    const int lane = tid & 31, wid = tid >> 5;
    const int wm = wid >> 2, wn = wid & 3;        // 2 x 4 warp grid
    const int grp = lane >> 2, qd = lane & 3;
    const int bm = blockIdx.y * 128, bn = blockIdx.x * 128;
    const int r0 = tid >> 2, c4 = (tid & 3) * 4, r1 = r0 + 64;

    const unsigned* Ar0 = A + (size_t)(bm + r0) * K + c4;
    const unsigned* Ar1 = A + (size_t)(bm + r1) * K + c4;
    const unsigned* Wr0 = W + (size_t)(bn + r0) * K + c4;
    const unsigned* Wr1 = W + (size_t)(bn + r1) * K + c4;

    const unsigned sa = (unsigned)__cvta_generic_to_shared(As);
    const unsigned sb = (unsigned)__cvta_generic_to_shared(Bs);
    const unsigned dA0 = sa + (r0*20 + c4)*4, dA1 = sa + (r1*20 + c4)*4;
    const unsigned dB0 = sb + (r0*20 + c4)*4, dB1 = sb + (r1*20 + c4)*4;
    const unsigned SLOTB = GEMM_SLOT*4;

    const int ktot = K / 16;

    float acc[4][4][4];
#pragma unroll
    for (int i = 0; i < 4; i++)
#pragma unroll
        for (int j = 0; j < 4; j++)
#pragma unroll
            for (int x = 0; x < 4; x++) acc[i][j][x] = 0.f;

#pragma unroll
    for (int p = 0; p < 3; p++) {
        const unsigned off = p * SLOTB;
        cp16(dA0 + off, Ar0 + p*16); cp16(dA1 + off, Ar1 + p*16);
        cp16(dB0 + off, Wr0 + p*16); cp16(dB1 + off, Wr1 + p*16);
        asm volatile("cp.async.commit_group;" ::: "memory");
    }

    for (int kt = 0; kt < ktot; kt++) {
        asm volatile("cp.async.wait_group 2;" ::: "memory");
        __syncthreads();
        if (kt + 3 < ktot) {
            const int sl = (kt + 3) & 3;
            const unsigned off = sl * SLOTB;
            cp16(dA0 + off, Ar0 + (kt+3)*16); cp16(dA1 + off, Ar1 + (kt+3)*16);
            cp16(dB0 + off, Wr0 + (kt+3)*16); cp16(dB1 + off, Wr1 + (kt+3)*16);
        }
        asm volatile("cp.async.commit_group;" ::: "memory");

        const unsigned* Asl = As + (kt & 3) * GEMM_SLOT;
        const unsigned* Bsl = Bs + (kt & 3) * GEMM_SLOT;
#pragma unroll
        for (int k8 = 0; k8 < 16; k8 += 8) {
            unsigned a[4][4], b[4][2];
#pragma unroll
            for (int mi = 0; mi < 4; mi++) {
                const int r = wm*64 + mi*16 + grp;
                a[mi][0] = Asl[r*20 + k8 + qd];
                a[mi][1] = Asl[(r+8)*20 + k8 + qd];
                a[mi][2] = Asl[r*20 + k8 + qd + 4];
                a[mi][3] = Asl[(r+8)*20 + k8 + qd + 4];
            }
#pragma unroll
            for (int ni = 0; ni < 4; ni++) {
                const int n = wn*32 + ni*8 + grp;
                b[ni][0] = Bsl[n*20 + k8 + qd];
                b[ni][1] = Bsl[n*20 + k8 + qd + 4];
            }
#pragma unroll
            for (int mi = 0; mi < 4; mi++)
#pragma unroll
                for (int ni = 0; ni < 4; ni++)
                    mma8(acc[mi][ni], a[mi], b[ni][0], b[ni][1]);
        }
    }

#pragma unroll
    for (int mi = 0; mi < 4; mi++) {
        const int row = bm + wm*64 + mi*16 + grp;
#pragma unroll
        for (int ni = 0; ni < 4; ni++) {
            const int col = bn + wn*32 + ni*8 + qd*2;
            float g0 = bias[col], g1 = bias[col+1];
            float o0 = acc[mi][ni][0] + g0, o1 = acc[mi][ni][1] + g1;
            float o2 = acc[mi][ni][2] + g0, o3 = acc[mi][ni][3] + g1;
            if (OUT_T32) {
                o0=fmaxf(o0,0.f); o1=fmaxf(o1,0.f); o2=fmaxf(o2,0.f); o3=fmaxf(o3,0.f);
                unsigned* Cu = (unsigned*)Cout;
                *(uint2*)(Cu + (size_t)row    * N + col) = make_uint2(f2t(o0), f2t(o1));
                *(uint2*)(Cu + (size_t)(row+8)* N + col) = make_uint2(f2t(o2), f2t(o3));
            } else {
                float* Cf = (float*)Cout;
                *(float2*)(Cf + (size_t)row    * N + col) = make_float2(o0, o1);
                *(float2*)(Cf + (size_t)(row+8)* N + col) = make_float2(o2, o3);
            }
        }
    }
}

// ---------------------------------------------------------------------------
// Fused flash attention. Output written as tf32 (u32) in [s*B+b, h*64+d].
// Skips fully-masked key tiles (mask is monotone: pad is a suffix).
// ---------------------------------------------------------------------------
__global__ __launch_bounds__(256, 2)
void flash_attn(const float* __restrict__ Q, const float* __restrict__ K,
                const float* __restrict__ V, const void* __restrict__ mask,
                unsigned* __restrict__ O)
{
    extern __shared__ unsigned smem_u[];
    unsigned* Qs = smem_u;                 // 128*68
    unsigned* Ks = Qs + 128*68;            // 64*68
    unsigned* Vs = Ks + 64*68;             // 64*72
    unsigned* Ps = Vs + 64*72;             // 128*68
    float* redm = (float*)(Ps + 128*68);   // 256
    float* redl = redm + 256;              // 256
    unsigned char* msk = (unsigned char*)(redl + 256);  // 2048
    __shared__ int s_end;

    const int tid = threadIdx.x, lane = tid & 31, wid = tid >> 5;
    const int wm = wid >> 1, wn = wid & 1;       // 4 x 2 warps, 32x32 tiles
    const int grp = lane >> 2, qd = lane & 3;
    const int bh = blockIdx.y, b = bh >> 4, h = bh & 15;
    const int bm = blockIdx.x * 128;

    const float* qb = Q + b*DMODEL + h*HDIM;
    const float* kb = K + b*DMODEL + h*HDIM;
    const float* vb = V + b*DMODEL + h*HDIM;

    if (tid == 0) s_end = SLEN;
    // mask row -> smem (u8-bool or int32 probed at runtime)
    {
        const unsigned char* m8  = (const unsigned char*)mask;
        const int*           m32 = (const int*)mask;
        const bool isu8 = (m8[SLEN - 1] == 1);
        for (int t = tid; t < SLEN; t += 256)
            msk[t] = isu8 ? (m8[(size_t)b*SLEN + t] != 0)
                          : (m32[(size_t)b*SLEN + t] != 0);
    }
    // Q tile -> smem, pre-scaled by 1/8
    {
        const int r = tid >> 4, c = (tid & 15) * 4;
#pragma unroll
        for (int p = 0; p < 8; p++) {
            const int rr = r + p*16;
            float4 v4 = *(const float4*)(qb + (size_t)(bm + rr) * LDAQ + c);
            unsigned* d = &Qs[rr*68 + c];
            d[0]=f2t(v4.x*0.125f); d[1]=f2t(v4.y*0.125f);
            d[2]=f2t(v4.z*0.125f); d[3]=f2t(v4.w*0.125f);
        }
    }
    __syncthreads();
    // first masked key (mask is monotone suffix)
    {
        int lm = SLEN;
        for (int t = tid; t < SLEN; t += 256)
            if (msk[t]) { lm = t; break; }
        if (lm < SLEN) atomicMin(&s_end, lm);
    }
    __syncthreads();
    const int kv_end = min(SLEN, (s_end + 63) & ~63);

    float m_st[2][2], l_st[2][2];
    float oacc[2][4][4];
#pragma unroll
    for (int mi = 0; mi < 2; mi++) {
        m_st[mi][0] = -INFINITY; m_st[mi][1] = -INFINITY;
        l_st[mi][0] = 0.f;       l_st[mi][1] = 0.f;
#pragma unroll
        for (int ni = 0; ni < 4; ni++)
#pragma unroll
            for (int x = 0; x < 4; x++) oacc[mi][ni][x] = 0.f;
    }

    const int rkv = tid >> 4, ckv = (tid & 15) * 4;

    for (int kt = 0; kt < kv_end; kt += 64) {
        __syncthreads();
#pragma unroll
        for (int p = 0; p < 4; p++) {
            const int rr = rkv + p*16;
            float4 k4 = *(const float4*)(kb + (size_t)(kt + rr) * LDAQ + ckv);
            float4 v4 = *(const float4*)(vb + (size_t)(kt + rr) * LDAQ + ckv);
            unsigned* dk = &Ks[rr*68 + ckv];
            dk[0]=f2t(k4.x); dk[1]=f2t(k4.y); dk[2]=f2t(k4.z); dk[3]=f2t(k4.w);
            unsigned* dv = &Vs[rr*72 + ckv];
            dv[0]=f2t(v4.x); dv[1]=f2t(v4.y); dv[2]=f2t(v4.z); dv[3]=f2t(v4.w);
        }
        __syncthreads();

        float sacc[2][4][4];
#pragma unroll
        for (int mi = 0; mi < 2; mi++)
#pragma unroll
            for (int ni = 0; ni < 4; ni++)
#pragma unroll
                for (int x = 0; x < 4; x++) sacc[mi][ni][x] = 0.f;
#pragma unroll
        for (int k8 = 0; k8 < 64; k8 += 8) {
            unsigned a[2][4], bb[4][2];
#pragma unroll
            for (int mi = 0; mi < 2; mi++) {
                const int r = wm*32 + mi*16 + grp;
                a[mi][0] = Qs[r*68 + k8 + qd];
                a[mi][1] = Qs[(r+8)*68 + k8 + qd];
                a[mi][2] = Qs[r*68 + k8 + qd + 4];
                a[mi][3] = Qs[(r+8)*68 + k8 + qd + 4];
            }
#pragma unroll
            for (int ni = 0; ni < 4; ni++) {
                const int n = wn*32 + ni*8 + grp;
                bb[ni][0] = Ks[n*68 + k8 + qd];
                bb[ni][1] = Ks[n*68 + k8 + qd + 4];
            }
#pragma unroll
            for (int mi = 0; mi < 2; mi++)
#pragma unroll
                for (int ni = 0; ni < 4; ni++)
                    mma8(sacc[mi][ni], a[mi], bb[ni][0], bb[ni][1]);
        }
        // mask
#pragma unroll
        for (int ni = 0; ni < 4; ni++) {
            const int c0 = kt + wn*32 + ni*8 + qd*2;
            if (msk[c0]) {
                sacc[0][ni][0] = -INFINITY; sacc[0][ni][2] = -INFINITY;
                sacc[1][ni][0] = -INFINITY; sacc[1][ni][2] = -INFINITY;
            }
            if (msk[c0+1]) {
                sacc[0][ni][1] = -INFINITY; sacc[0][ni][3] = -INFINITY;
                sacc[1][ni][1] = -INFINITY; sacc[1][ni][3] = -INFINITY;
            }
        }
        // row max
#pragma unroll
        for (int mi = 0; mi < 2; mi++)
#pragma unroll
            for (int hf = 0; hf < 2; hf++) {
                float mx = -INFINITY;
#pragma unroll
                for (int ni = 0; ni < 4; ni++)
                    mx = fmaxf(mx, fmaxf(sacc[mi][ni][hf*2], sacc[mi][ni][hf*2+1]));
                mx = fmaxf(mx, __shfl_xor_sync(0xffffffffu, mx, 1));
                mx = fmaxf(mx, __shfl_xor_sync(0xffffffffu, mx, 2));
                if (qd == 0) redm[wn*128 + wm*32 + mi*16 + hf*8 + grp] = mx;
            }
        __syncthreads();

        float sc[2][2];
#pragma unroll
        for (int mi = 0; mi < 2; mi++)
#pragma unroll
            for (int hf = 0; hf < 2; hf++) {
                const int row = wm*32 + mi*16 + hf*8 + grp;
                const float tm = fmaxf(redm[row], redm[128 + row]);
                const float mnew = fmaxf(m_st[mi][hf], tm);
                sc[mi][hf] = __expf(m_st[mi][hf] - mnew);
                m_st[mi][hf] = mnew;
            }
        float ls[2][2] = {{0.f,0.f},{0.f,0.f}};
#pragma unroll
        for (int mi = 0; mi < 2; mi++) {
            const int r = wm*32 + mi*16 + grp;
#pragma unroll
            for (int ni = 0; ni < 4; ni++) {
                const int c = wn*32 + ni*8 + qd*2;
                float p0 = __expf(sacc[mi][ni][0] - m_st[mi][0]);
                float p1 = __expf(sacc[mi][ni][1] - m_st[mi][0]);
                float p2 = __expf(sacc[mi][ni][2] - m_st[mi][1]);
                float p3 = __expf(sacc[mi][ni][3] - m_st[mi][1]);
                ls[mi][0] += p0 + p1;
                ls[mi][1] += p2 + p3;
                Ps[r*68 + c]     = f2t(p0); Ps[r*68 + c + 1]     = f2t(p1);
                Ps[(r+8)*68 + c] = f2t(p2); Ps[(r+8)*68 + c + 1] = f2t(p3);
            }
        }
#pragma unroll
        for (int mi = 0; mi < 2; mi++)
#pragma unroll
            for (int hf = 0; hf < 2; hf++) {
                float s = ls[mi][hf];
                s += __shfl_xor_sync(0xffffffffu, s, 1);
                s += __shfl_xor_sync(0xffffffffu, s, 2);
                if (qd == 0) redl[wn*128 + wm*32 + mi*16 + hf*8 + grp] = s;
            }
        __syncthreads();
#pragma unroll
        for (int mi = 0; mi < 2; mi++)
#pragma unroll
            for (int hf = 0; hf < 2; hf++) {
                const int row = wm*32 + mi*16 + hf*8 + grp;
                l_st[mi][hf] = l_st[mi][hf] * sc[mi][hf] + redl[row] + redl[128 + row];
            }
#pragma unroll
        for (int mi = 0; mi < 2; mi++)
#pragma unroll
            for (int ni = 0; ni < 4; ni++) {
                oacc[mi][ni][0] *= sc[mi][0]; oacc[mi][ni][1] *= sc[mi][0];
                oacc[mi][ni][2] *= sc[mi][1]; oacc[mi][ni][3] *= sc[mi][1];
            }
#pragma unroll
        for (int k8 = 0; k8 < 64; k8 += 8) {
            unsigned a[2][4], bb[4][2];
#pragma unroll
            for (int mi = 0; mi < 2; mi++) {
                const int r = wm*32 + mi*16 + grp;
                a[mi][0] = Ps[r*68 + k8 + qd];
                a[mi][1] = Ps[(r+8)*68 + k8 + qd];
                a[mi][2] = Ps[r*68 + k8 + qd + 4];
                a[mi][3] = Ps[(r+8)*68 + k8 + qd + 4];
            }
#pragma unroll
            for (int ni = 0; ni < 4; ni++) {
                const int n = wn*32 + ni*8 + grp;
                bb[ni][0] = Vs[(k8 + qd)*72 + n];
                bb[ni][1] = Vs[(k8 + qd + 4)*72 + n];
            }
#pragma unroll
            for (int mi = 0; mi < 2; mi++)
#pragma unroll
                for (int ni = 0; ni < 4; ni++)
                    mma8(oacc[mi][ni], a[mi], bb[ni][0], bb[ni][1]);
        }
    }

    // epilogue: O = tf32(O / l)
#pragma unroll
    for (int mi = 0; mi < 2; mi++) {
        const int s0 = bm + wm*32 + mi*16 + grp;
        const float inv0 = 1.f / l_st[mi][0];
        const float inv1 = 1.f / l_st[mi][1];
#pragma unroll
        for (int ni = 0; ni < 4; ni++) {
            const int c = h*HDIM + wn*32 + ni*8 + qd*2;
            unsigned* o0 = O + ((size_t)s0     * BATCH + b) * DMODEL + c;
            unsigned* o1 = O + ((size_t)(s0+8) * BATCH + b) * DMODEL + c;
            *(uint2*)o0 = make_uint2(f2t(oacc[mi][ni][0]*inv0), f2t(oacc[mi][ni][1]*inv0));
            *(uint2*)o1 = make_uint2(f2t(oacc[mi][ni][2]*inv1), f2t(oacc[mi][ni][3]*inv1));
        }
    }
}

// ---------------------------------------------------------------------------
// out = LayerNorm(y + res) * g + b; optionally also writes tf32 copy.
// ---------------------------------------------------------------------------
template<bool DUAL>
__global__ void add_ln(const float* __restrict__ y, const float* __restrict__ res,
                       const float* __restrict__ g, const float* __restrict__ be,
                       float* __restrict__ out, unsigned* __restrict__ out_t)
{
    const int r   = blockIdx.x;
    const int tid = threadIdx.x;
    const float4 a  = ((const float4*)(y   + (size_t)r*DMODEL))[tid];
    const float4 b4 = ((const float4*)(res + (size_t)r*DMODEL))[tid];
    float x0 = a.x + b4.x, x1 = a.y + b4.y, x2 = a.z + b4.z, x3 = a.w + b4.w;
    float s = x0 + x1 + x2 + x3;
    float q = x0*x0 + x1*x1 + x2*x2 + x3*x3;

    __shared__ float rs[8], rq[8];
#pragma unroll
    for (int o = 16; o; o >>= 1) {
        s += __shfl_xor_sync(0xffffffffu, s, o);
        q += __shfl_xor_sync(0xffffffffu, q, o);
    }
    if ((tid & 31) == 0) { rs[tid >> 5] = s; rq[tid >> 5] = q; }
    __syncthreads();
    float st = 0.f, qt = 0.f;
#pragma unroll
    for (int i = 0; i < 8; i++) { st += rs[i]; qt += rq[i]; }
    const float mean = st * (1.f/1024.f);
    const float var  = qt * (1.f/1024.f) - mean*mean;
    const float rstd = rsqrtf(var + 1e-5f);

    const float4 gv = ((const float4*)g)[tid];
    const float4 bv = ((const float4*)be)[tid];
    float4 o;
    o.x = (x0 - mean) * rstd * gv.x + bv.x;
    o.y = (x1 - mean) * rstd * gv.y + bv.y;
    o.z = (x2 - mean) * rstd * gv.z + bv.z;
    o.w = (x3 - mean) * rstd * gv.w + bv.w;
    ((float4*)(out + (size_t)r*DMODEL))[tid] = o;
    if (DUAL) {
        uint4 u = make_uint4(f2t(o.x), f2t(o.y), f2t(o.z), f2t(o.w));
        ((uint4*)(out_t + (size_t)r*DMODEL))[tid] = u;
    }
}

// ---------------------------------------------------------------------------
#define FLASH_SMEM ((128*68 + 64*68 + 64*72 + 128*68) * 4 + 256*4*2 + 2048)

extern "C" void kernel_launch(void* const* d_in, const int* in_sizes, int n_in,
                              void* d_out, int out_size)
{
    const float* state = (const float*)d_in[0];
    const void*  mask  = d_in[1];
    const float* Wq = (const float*)d_in[2];  const float* bq = (const float*)d_in[3];
    const float* Wk = (const float*)d_in[4];  const float* bk = (const float*)d_in[5];
    const float* Wv = (const float*)d_in[6];  const float* bv = (const float*)d_in[7];
    const float* Wo = (const float*)d_in[8];  const float* bo = (const float*)d_in[9];
    const float* g1 = (const float*)d_in[10]; const float* be1 = (const float*)d_in[11];
    const float* W1 = (const float*)d_in[12]; const float* b1 = (const float*)d_in[13];
    const float* W2 = (const float*)d_in[14]; const float* b2 = (const float*)d_in[15];
    const float* g2 = (const float*)d_in[16]; const float* be2 = (const float*)d_in[17];
    float* out = (float*)d_out;

    unsigned *state_t, *wq_t, *wk_t, *wv_t, *wo_t, *w1_t, *w2_t;
    unsigned *att_t, *x1_t, *h_t;
    float *q, *k, *v, *y, *x1, *y2;
    cudaGetSymbolAddress((void**)&state_t, g_state_t);
    cudaGetSymbolAddress((void**)&wq_t, g_wq_t);
    cudaGetSymbolAddress((void**)&wk_t, g_wk_t);
    cudaGetSymbolAddress((void**)&wv_t, g_wv_t);
    cudaGetSymbolAddress((void**)&wo_t, g_wo_t);
    cudaGetSymbolAddress((void**)&w1_t, g_w1_t);
    cudaGetSymbolAddress((void**)&w2_t, g_w2_t);
    cudaGetSymbolAddress((void**)&q,   g_q);
    cudaGetSymbolAddress((void**)&k,   g_k);
    cudaGetSymbolAddress((void**)&v,   g_v);
    cudaGetSymbolAddress((void**)&att_t, g_att_t);
    cudaGetSymbolAddress((void**)&y,   g_y);
    cudaGetSymbolAddress((void**)&x1,  g_x1);
    cudaGetSymbolAddress((void**)&x1_t, g_x1_t);
    cudaGetSymbolAddress((void**)&h_t, g_h_t);
    cudaGetSymbolAddress((void**)&y2,  g_y2);

    cudaFuncSetAttribute(flash_attn, cudaFuncAttributeMaxDynamicSharedMemorySize,
                         FLASH_SMEM);
    cudaFuncSetAttribute(gemm_tt<false>, cudaFuncAttributeMaxDynamicSharedMemorySize,
                         GEMM_SMEM);
    cudaFuncSetAttribute(gemm_tt<true>, cudaFuncAttributeMaxDynamicSharedMemorySize,
                         GEMM_SMEM);

    const dim3 thr(256);
    // converts (state + weights)
    f2t_kernel<<<(NROW*DMODEL/4 + 255)/256, 256>>>(state, state_t, NROW*DMODEL/4);
    f2t_kernel<<<(DMODEL*DMODEL/4 + 255)/256, 256>>>(Wq, wq_t, DMODEL*DMODEL/4);
    f2t_kernel<<<(DMODEL*DMODEL/4 + 255)/256, 256>>>(Wk, wk_t, DMODEL*DMODEL/4);
    f2t_kernel<<<(DMODEL*DMODEL/4 + 255)/256, 256>>>(Wv, wv_t, DMODEL*DMODEL/4);
    f2t_kernel<<<(DMODEL*DMODEL/4 + 255)/256, 256>>>(Wo, wo_t, DMODEL*DMODEL/4);
    f2t_kernel<<<(FFDIM*DMODEL/4 + 255)/256, 256>>>(W1, w1_t, FFDIM*DMODEL/4);
    f2t_kernel<<<(DMODEL*FFDIM/4 + 255)/256, 256>>>(W2, w2_t, DMODEL*FFDIM/4);
    // QKV projections
    gemm_tt<false><<<dim3(DMODEL/128, NROW/128), thr, GEMM_SMEM>>>(state_t, wq_t, bq, q, DMODEL, DMODEL);
    gemm_tt<false><<<dim3(DMODEL/128, NROW/128), thr, GEMM_SMEM>>>(state_t, wk_t, bk, k, DMODEL, DMODEL);
    gemm_tt<false><<<dim3(DMODEL/128, NROW/128), thr, GEMM_SMEM>>>(state_t, wv_t, bv, v, DMODEL, DMODEL);
    // fused attention -> tf32 output
    flash_attn<<<dim3(SLEN/128, BATCH*NHEAD), thr, FLASH_SMEM>>>(q, k, v, mask, att_t);
    // output projection + LN1 (dual write)
    gemm_tt<false><<<dim3(DMODEL/128, NROW/128), thr, GEMM_SMEM>>>(att_t, wo_t, bo, y, DMODEL, DMODEL);
    add_ln<true><<<NROW, 256>>>(y, state, g1, be1, x1, x1_t);
    // FFN (FF1 writes tf32 with ReLU) + LN2
    gemm_tt<true ><<<dim3(FFDIM/128, NROW/128), thr, GEMM_SMEM>>>(x1_t, w1_t, b1, h_t, FFDIM, DMODEL);
    gemm_tt<false><<<dim3(DMODEL/128, NROW/128), thr, GEMM_SMEM>>>(h_t, w2_t, b2, y2, DMODEL, FFDIM);
    add_ln<false><<<NROW, 256>>>(y2, x1, g2, be2, out, nullptr);
}

// round 7
// speedup vs baseline: 3.5921x; 1.2270x over previous
#include <cuda_runtime.h>
#include <math.h>

#define SLEN 2048
#define BATCH 4
#define DMODEL 1024
#define NHEAD 16
#define HDIM 64
#define FFDIM 4096
#define NROW (SLEN*BATCH)      /* 8192 */
#define LDAQ (BATCH*DMODEL)    /* 4096 */

// ------------------------- static scratch -----------------------------------
__device__ unsigned g_state_t[NROW*DMODEL];
__device__ unsigned g_wq_t[DMODEL*DMODEL];
__device__ unsigned g_wk_t[DMODEL*DMODEL];
__device__ unsigned g_wv_t[DMODEL*DMODEL];
__device__ unsigned g_wo_t[DMODEL*DMODEL];
__device__ unsigned g_w1_t[FFDIM*DMODEL];
__device__ unsigned g_w2_t[DMODEL*FFDIM];
__device__ float    g_q  [NROW*DMODEL];
__device__ float    g_k  [NROW*DMODEL];
__device__ float    g_v  [NROW*DMODEL];
__device__ unsigned g_att_t[NROW*DMODEL];
__device__ float    g_y  [NROW*DMODEL];
__device__ float    g_x1 [NROW*DMODEL];
__device__ unsigned g_x1_t[NROW*DMODEL];
__device__ unsigned g_h_t[NROW*FFDIM];
__device__ float    g_y2 [NROW*DMODEL];

// --------------------------- helpers ----------------------------------------
__device__ __forceinline__ unsigned f2t(float f) {
    unsigned u; asm("cvt.rna.tf32.f32 %0, %1;" : "=r"(u) : "f"(f)); return u;
}
__device__ __forceinline__ void mma8(float* c, const unsigned* a, unsigned b0, unsigned b1) {
    asm("mma.sync.aligned.m16n8k8.row.col.f32.tf32.tf32.f32 "
        "{%0,%1,%2,%3},{%4,%5,%6,%7},{%8,%9},{%0,%1,%2,%3};"
        : "+f"(c[0]), "+f"(c[1]), "+f"(c[2]), "+f"(c[3])
        : "r"(a[0]), "r"(a[1]), "r"(a[2]), "r"(a[3]), "r"(b0), "r"(b1));
}
__device__ __forceinline__ void cp16(unsigned dst, const void* src) {
    asm volatile("cp.async.ca.shared.global [%0], [%1], 16;" :: "r"(dst), "l"(src));
}
__device__ __forceinline__ void ldm4(unsigned& r0, unsigned& r1, unsigned& r2, unsigned& r3,
                                     unsigned addr) {
    asm volatile("ldmatrix.sync.aligned.m8n8.x4.shared.b16 {%0,%1,%2,%3}, [%4];"
                 : "=r"(r0), "=r"(r1), "=r"(r2), "=r"(r3) : "r"(addr));
}

// fp32 -> tf32 bulk convert (n divisible by 4)
__global__ void f2t_kernel(const float* __restrict__ in, unsigned* __restrict__ out, int n4)
{
    int i = blockIdx.x * blockDim.x + threadIdx.x;
    if (i < n4) {
        float4 v = ((const float4*)in)[i];
        uint4 o = make_uint4(f2t(v.x), f2t(v.y), f2t(v.z), f2t(v.w));
        ((uint4*)out)[i] = o;
    }
}

// ---------------------------------------------------------------------------
// Dense GEMM body on pre-converted tf32:  C[M,N] = A[M,K] * W[N,K]^T + bias
// 128x128x16 tiles, 4-stage cp.async pipeline (80KB dyn smem),
// warp 64x32 mma tiles, ldmatrix fragment loads.
// ---------------------------------------------------------------------------
#define GEMM_SLOT (128*20)
#define GEMM_SMEM (4*GEMM_SLOT*2*4)

template<bool OUT_T32>
__device__ __forceinline__
void gemm_body(const unsigned* __restrict__ A, const unsigned* __restrict__ W,
               const float* __restrict__ bias, void* __restrict__ Cout,
               int N, int K, unsigned* gs, int bm, int bn)
{
    unsigned* As = gs;
    unsigned* Bs = gs + 4*GEMM_SLOT;
    const int tid  = threadIdx.x;
    const int lane = tid & 31, wid = tid >> 5;
    const int wm = wid >> 2, wn = wid & 3;
    const int grp = lane >> 2, qd = lane & 3;
    const int r0 = tid >> 2, c4 = (tid & 3) * 4, r1 = r0 + 64;
    const int row_in = lane & 7, mat = lane >> 3;

    const unsigned* Ar0 = A + (size_t)(bm + r0) * K + c4;
    const unsigned* Ar1 = A + (size_t)(bm + r1) * K + c4;
    const unsigned* Wr0 = W + (size_t)(bn + r0) * K + c4;
    const unsigned* Wr1 = W + (size_t)(bn + r1) * K + c4;

    const unsigned sa = (unsigned)__cvta_generic_to_shared(As);
    const unsigned sb = (unsigned)__cvta_generic_to_shared(Bs);
    const unsigned dA0 = sa + (r0*20 + c4)*4, dA1 = sa + (r1*20 + c4)*4;
    const unsigned dB0 = sb + (r0*20 + c4)*4, dB1 = sb + (r1*20 + c4)*4;
    const unsigned SLOTB = GEMM_SLOT*4;

    // ldmatrix lane bases (bytes)
    const unsigned a_lane = ((wm*64 + (mat&1)*8 + row_in) * 20 + (mat>>1)*4) * 4;
    const unsigned b_lane = ((wn*32 + (mat>>1)*8 + row_in) * 20 + (mat&1)*4) * 4;

    const int ktot = K / 16;

    float acc[4][4][4];
#pragma unroll
    for (int i = 0; i < 4; i++)
#pragma unroll
        for (int j = 0; j < 4; j++)
#pragma unroll
            for (int x = 0; x < 4; x++) acc[i][j][x] = 0.f;

#pragma unroll
    for (int p = 0; p < 3; p++) {
        const unsigned off = p * SLOTB;
        cp16(dA0 + off, Ar0 + p*16); cp16(dA1 + off, Ar1 + p*16);
        cp16(dB0 + off, Wr0 + p*16); cp16(dB1 + off, Wr1 + p*16);
        asm volatile("cp.async.commit_group;" ::: "memory");
    }

    for (int kt = 0; kt < ktot; kt++) {
        asm volatile("cp.async.wait_group 2;" ::: "memory");
        __syncthreads();
        if (kt + 3 < ktot) {
            const unsigned off = ((kt + 3) & 3) * SLOTB;
            cp16(dA0 + off, Ar0 + (kt+3)*16); cp16(dA1 + off, Ar1 + (kt+3)*16);
            cp16(dB0 + off, Wr0 + (kt+3)*16); cp16(dB1 + off, Wr1 + (kt+3)*16);
        }
        asm volatile("cp.async.commit_group;" ::: "memory");

        const unsigned slotA = sa + (kt & 3) * SLOTB;
        const unsigned slotB = sb + (kt & 3) * SLOTB;
#pragma unroll
        for (int k8 = 0; k8 < 16; k8 += 8) {
            unsigned a[4][4], b[4][2];
#pragma unroll
            for (int mi = 0; mi < 4; mi++)
                ldm4(a[mi][0], a[mi][1], a[mi][2], a[mi][3],
                     slotA + a_lane + (mi*16*20 + k8)*4);
#pragma unroll
            for (int g = 0; g < 2; g++)
                ldm4(b[2*g][0], b[2*g][1], b[2*g+1][0], b[2*g+1][1],
                     slotB + b_lane + (g*16*20 + k8)*4);
#pragma unroll
            for (int mi = 0; mi < 4; mi++)
#pragma unroll
                for (int ni = 0; ni < 4; ni++)
                    mma8(acc[mi][ni], a[mi], b[ni][0], b[ni][1]);
        }
    }

#pragma unroll
    for (int mi = 0; mi < 4; mi++) {
        const int row = bm + wm*64 + mi*16 + grp;
#pragma unroll
        for (int ni = 0; ni < 4; ni++) {
            const int col = bn + wn*32 + ni*8 + qd*2;
            float g0 = bias[col], g1 = bias[col+1];
            float o0 = acc[mi][ni][0] + g0, o1 = acc[mi][ni][1] + g1;
            float o2 = acc[mi][ni][2] + g0, o3 = acc[mi][ni][3] + g1;
            if (OUT_T32) {
                o0=fmaxf(o0,0.f); o1=fmaxf(o1,0.f); o2=fmaxf(o2,0.f); o3=fmaxf(o3,0.f);
                unsigned* Cu = (unsigned*)Cout;
                *(uint2*)(Cu + (size_t)row    * N + col) = make_uint2(f2t(o0), f2t(o1));
                *(uint2*)(Cu + (size_t)(row+8)* N + col) = make_uint2(f2t(o2), f2t(o3));
            } else {
                float* Cf = (float*)Cout;
                *(float2*)(Cf + (size_t)row    * N + col) = make_float2(o0, o1);
                *(float2*)(Cf + (size_t)(row+8)* N + col) = make_float2(o2, o3);
            }
        }
    }
}

template<bool OUT_T32>
__global__ __launch_bounds__(256, 2)
void gemm_tt(const unsigned* __restrict__ A, const unsigned* __restrict__ W,
             const float* __restrict__ bias, void* __restrict__ Cout, int N, int K)
{
    extern __shared__ unsigned gs[];
    gemm_body<OUT_T32>(A, W, bias, Cout, N, K, gs, blockIdx.y*128, blockIdx.x*128);
}

// fused QKV: blockIdx.z selects weight/bias/output
__global__ __launch_bounds__(256, 2)
void gemm_qkv(const unsigned* __restrict__ A,
              const unsigned* __restrict__ Wq, const unsigned* __restrict__ Wk,
              const unsigned* __restrict__ Wv,
              const float* __restrict__ bq, const float* __restrict__ bk,
              const float* __restrict__ bv,
              float* __restrict__ Cq, float* __restrict__ Ck, float* __restrict__ Cv)
{
    extern __shared__ unsigned gs[];
    const int z = blockIdx.z;
    const unsigned* W = (z == 0) ? Wq : (z == 1) ? Wk : Wv;
    const float* bias  = (z == 0) ? bq : (z == 1) ? bk : bv;
    float* C           = (z == 0) ? Cq : (z == 1) ? Ck : Cv;
    gemm_body<false>(A, W, bias, C, DMODEL, DMODEL, gs, blockIdx.y*128, blockIdx.x*128);
}

// ---------------------------------------------------------------------------
// Fused flash attention, ldmatrix fragment loads for Q/K/P. tf32 output.
// ---------------------------------------------------------------------------
__global__ __launch_bounds__(256, 2)
void flash_attn(const float* __restrict__ Q, const float* __restrict__ K,
                const float* __restrict__ V, const void* __restrict__ mask,
                unsigned* __restrict__ O)
{
    extern __shared__ unsigned smem_u[];
    unsigned* Qs = smem_u;                 // 128*68
    unsigned* Ks = Qs + 128*68;            // 64*68
    unsigned* Vs = Ks + 64*68;             // 64*72
    unsigned* Ps = Vs + 64*72;             // 128*68
    float* redm = (float*)(Ps + 128*68);   // 256
    float* redl = redm + 256;              // 256
    unsigned char* msk = (unsigned char*)(redl + 256);  // 2048
    __shared__ int s_end;

    const int tid = threadIdx.x, lane = tid & 31, wid = tid >> 5;
    const int wm = wid >> 1, wn = wid & 1;       // 4 x 2 warps, 32x32 tiles
    const int grp = lane >> 2, qd = lane & 3;
    const int row_in = lane & 7, mat = lane >> 3;
    const int bh = blockIdx.y, b = bh >> 4, h = bh & 15;
    const int bm = blockIdx.x * 128;

    const float* qb = Q + b*DMODEL + h*HDIM;
    const float* kb = K + b*DMODEL + h*HDIM;
    const float* vb = V + b*DMODEL + h*HDIM;

    const unsigned sQ = (unsigned)__cvta_generic_to_shared(Qs);
    const unsigned sK = (unsigned)__cvta_generic_to_shared(Ks);
    const unsigned sP = (unsigned)__cvta_generic_to_shared(Ps);
    // lane bases (bytes): A-type tiles pitch 68
    const unsigned aq_lane = ((wm*32 + (mat&1)*8 + row_in) * 68 + (mat>>1)*4) * 4;
    const unsigned bk_lane = ((wn*32 + (mat>>1)*8 + row_in) * 68 + (mat&1)*4) * 4;

    if (tid == 0) s_end = SLEN;
    {
        const unsigned char* m8  = (const unsigned char*)mask;
        const int*           m32 = (const int*)mask;
        const bool isu8 = (m8[SLEN - 1] == 1);
        for (int t = tid; t < SLEN; t += 256)
            msk[t] = isu8 ? (m8[(size_t)b*SLEN + t] != 0)
                          : (m32[(size_t)b*SLEN + t] != 0);
    }
    {
        const int r = tid >> 4, c = (tid & 15) * 4;
#pragma unroll
        for (int p = 0; p < 8; p++) {
            const int rr = r + p*16;
            float4 v4 = *(const float4*)(qb + (size_t)(bm + rr) * LDAQ + c);
            unsigned* d = &Qs[rr*68 + c];
            d[0]=f2t(v4.x*0.125f); d[1]=f2t(v4.y*0.125f);
            d[2]=f2t(v4.z*0.125f); d[3]=f2t(v4.w*0.125f);
        }
    }
    __syncthreads();
    {
        int lm = SLEN;
        for (int t = tid; t < SLEN; t += 256)
            if (msk[t]) { lm = t; break; }
        if (lm < SLEN) atomicMin(&s_end, lm);
    }
    __syncthreads();
    const int kv_end = min(SLEN, (s_end + 63) & ~63);

    float m_st[2][2], l_st[2][2];
    float oacc[2][4][4];
#pragma unroll
    for (int mi = 0; mi < 2; mi++) {
        m_st[mi][0] = -INFINITY; m_st[mi][1] = -INFINITY;
        l_st[mi][0] = 0.f;       l_st[mi][1] = 0.f;
#pragma unroll
        for (int ni = 0; ni < 4; ni++)
#pragma unroll
            for (int x = 0; x < 4; x++) oacc[mi][ni][x] = 0.f;
    }

    const int rkv = tid >> 4, ckv = (tid & 15) * 4;

    for (int kt = 0; kt < kv_end; kt += 64) {
        __syncthreads();
#pragma unroll
        for (int p = 0; p < 4; p++) {
            const int rr = rkv + p*16;
            float4 k4 = *(const float4*)(kb + (size_t)(kt + rr) * LDAQ + ckv);
            float4 v4 = *(const float4*)(vb + (size_t)(kt + rr) * LDAQ + ckv);
            unsigned* dk = &Ks[rr*68 + ckv];
            dk[0]=f2t(k4.x); dk[1]=f2t(k4.y); dk[2]=f2t(k4.z); dk[3]=f2t(k4.w);
            unsigned* dv = &Vs[rr*72 + ckv];
            dv[0]=f2t(v4.x); dv[1]=f2t(v4.y); dv[2]=f2t(v4.z); dv[3]=f2t(v4.w);
        }
        __syncthreads();

        float sacc[2][4][4];
#pragma unroll
        for (int mi = 0; mi < 2; mi++)
#pragma unroll
            for (int ni = 0; ni < 4; ni++)
#pragma unroll
                for (int x = 0; x < 4; x++) sacc[mi][ni][x] = 0.f;
#pragma unroll
        for (int k8 = 0; k8 < 64; k8 += 8) {
            unsigned a[2][4], bb[4][2];
#pragma unroll
            for (int mi = 0; mi < 2; mi++)
                ldm4(a[mi][0], a[mi][1], a[mi][2], a[mi][3],
                     sQ + aq_lane + (mi*16*68 + k8)*4);
#pragma unroll
            for (int g = 0; g < 2; g++)
                ldm4(bb[2*g][0], bb[2*g][1], bb[2*g+1][0], bb[2*g+1][1],
                     sK + bk_lane + (g*16*68 + k8)*4);
#pragma unroll
            for (int mi = 0; mi < 2; mi++)
#pragma unroll
                for (int ni = 0; ni < 4; ni++)
                    mma8(sacc[mi][ni], a[mi], bb[ni][0], bb[ni][1]);
        }
        // mask
#pragma unroll
        for (int ni = 0; ni < 4; ni++) {
            const int c0 = kt + wn*32 + ni*8 + qd*2;
            if (msk[c0]) {
                sacc[0][ni][0] = -INFINITY; sacc[0][ni][2] = -INFINITY;
                sacc[1][ni][0] = -INFINITY; sacc[1][ni][2] = -INFINITY;
            }
            if (msk[c0+1]) {
                sacc[0][ni][1] = -INFINITY; sacc[0][ni][3] = -INFINITY;
                sacc[1][ni][1] = -INFINITY; sacc[1][ni][3] = -INFINITY;
            }
        }
        // row max
#pragma unroll
        for (int mi = 0; mi < 2; mi++)
#pragma unroll
            for (int hf = 0; hf < 2; hf++) {
                float mx = -INFINITY;
#pragma unroll
                for (int ni = 0; ni < 4; ni++)
                    mx = fmaxf(mx, fmaxf(sacc[mi][ni][hf*2], sacc[mi][ni][hf*2+1]));
                mx = fmaxf(mx, __shfl_xor_sync(0xffffffffu, mx, 1));
                mx = fmaxf(mx, __shfl_xor_sync(0xffffffffu, mx, 2));
                if (qd == 0) redm[wn*128 + wm*32 + mi*16 + hf*8 + grp] = mx;
            }
        __syncthreads();

        float sc[2][2];
#pragma unroll
        for (int mi = 0; mi < 2; mi++)
#pragma unroll
            for (int hf = 0; hf < 2; hf++) {
                const int row = wm*32 + mi*16 + hf*8 + grp;
                const float tm = fmaxf(redm[row], redm[128 + row]);
                const float mnew = fmaxf(m_st[mi][hf], tm);
                sc[mi][hf] = __expf(m_st[mi][hf] - mnew);
                m_st[mi][hf] = mnew;
            }
        float ls[2][2] = {{0.f,0.f},{0.f,0.f}};
#pragma unroll
        for (int mi = 0; mi < 2; mi++) {
            const int r = wm*32 + mi*16 + grp;
#pragma unroll
            for (int ni = 0; ni < 4; ni++) {
                const int c = wn*32 + ni*8 + qd*2;
                float p0 = __expf(sacc[mi][ni][0] - m_st[mi][0]);
                float p1 = __expf(sacc[mi][ni][1] - m_st[mi][0]);
                float p2 = __expf(sacc[mi][ni][2] - m_st[mi][1]);
                float p3 = __expf(sacc[mi][ni][3] - m_st[mi][1]);
                ls[mi][0] += p0 + p1;
                ls[mi][1] += p2 + p3;
                Ps[r*68 + c]     = f2t(p0); Ps[r*68 + c + 1]     = f2t(p1);
                Ps[(r+8)*68 + c] = f2t(p2); Ps[(r+8)*68 + c + 1] = f2t(p3);
            }
        }
#pragma unroll
        for (int mi = 0; mi < 2; mi++)
#pragma unroll
            for (int hf = 0; hf < 2; hf++) {
                float s = ls[mi][hf];
                s += __shfl_xor_sync(0xffffffffu, s, 1);
                s += __shfl_xor_sync(0xffffffffu, s, 2);
                if (qd == 0) redl[wn*128 + wm*32 + mi*16 + hf*8 + grp] = s;
            }
        __syncthreads();
#pragma unroll
        for (int mi = 0; mi < 2; mi++)
#pragma unroll
            for (int hf = 0; hf < 2; hf++) {
                const int row = wm*32 + mi*16 + hf*8 + grp;
                l_st[mi][hf] = l_st[mi][hf] * sc[mi][hf] + redl[row] + redl[128 + row];
            }
#pragma unroll
        for (int mi = 0; mi < 2; mi++)
#pragma unroll
            for (int ni = 0; ni < 4; ni++) {
                oacc[mi][ni][0] *= sc[mi][0]; oacc[mi][ni][1] *= sc[mi][0];
                oacc[mi][ni][2] *= sc[mi][1]; oacc[mi][ni][3] *= sc[mi][1];
            }
#pragma unroll
        for (int k8 = 0; k8 < 64; k8 += 8) {
            unsigned a[2][4], bb[4][2];
#pragma unroll
            for (int mi = 0; mi < 2; mi++)
                ldm4(a[mi][0], a[mi][1], a[mi][2], a[mi][3],
                     sP + aq_lane + (mi*16*68 + k8)*4);
#pragma unroll
            for (int ni = 0; ni < 4; ni++) {
                const int n = wn*32 + ni*8 + grp;
                bb[ni][0] = Vs[(k8 + qd)*72 + n];
                bb[ni][1] = Vs[(k8 + qd + 4)*72 + n];
            }
#pragma unroll
            for (int mi = 0; mi < 2; mi++)
#pragma unroll
                for (int ni = 0; ni < 4; ni++)
                    mma8(oacc[mi][ni], a[mi], bb[ni][0], bb[ni][1]);
        }
    }

    // epilogue
#pragma unroll
    for (int mi = 0; mi < 2; mi++) {
        const int s0 = bm + wm*32 + mi*16 + grp;
        const float inv0 = 1.f / l_st[mi][0];
        const float inv1 = 1.f / l_st[mi][1];
#pragma unroll
        for (int ni = 0; ni < 4; ni++) {
            const int c = h*HDIM + wn*32 + ni*8 + qd*2;
            unsigned* o0 = O + ((size_t)s0     * BATCH + b) * DMODEL + c;
            unsigned* o1 = O + ((size_t)(s0+8) * BATCH + b) * DMODEL + c;
            *(uint2*)o0 = make_uint2(f2t(oacc[mi][ni][0]*inv0), f2t(oacc[mi][ni][1]*inv0));
            *(uint2*)o1 = make_uint2(f2t(oacc[mi][ni][2]*inv1), f2t(oacc[mi][ni][3]*inv1));
        }
    }
}

// ---------------------------------------------------------------------------
// out = LayerNorm(y + res) * g + b; optionally also writes tf32 copy.
// ---------------------------------------------------------------------------
template<bool DUAL>
__global__ void add_ln(const float* __restrict__ y, const float* __restrict__ res,
                       const float* __restrict__ g, const float* __restrict__ be,
                       float* __restrict__ out, unsigned* __restrict__ out_t)
{
    const int r   = blockIdx.x;
    const int tid = threadIdx.x;
    const float4 a  = ((const float4*)(y   + (size_t)r*DMODEL))[tid];
    const float4 b4 = ((const float4*)(res + (size_t)r*DMODEL))[tid];
    float x0 = a.x + b4.x, x1 = a.y + b4.y, x2 = a.z + b4.z, x3 = a.w + b4.w;
    float s = x0 + x1 + x2 + x3;
    float q = x0*x0 + x1*x1 + x2*x2 + x3*x3;

    __shared__ float rs[8], rq[8];
#pragma unroll
    for (int o = 16; o; o >>= 1) {
        s += __shfl_xor_sync(0xffffffffu, s, o);
        q += __shfl_xor_sync(0xffffffffu, q, o);
    }
    if ((tid & 31) == 0) { rs[tid >> 5] = s; rq[tid >> 5] = q; }
    __syncthreads();
    float st = 0.f, qt = 0.f;
#pragma unroll
    for (int i = 0; i < 8; i++) { st += rs[i]; qt += rq[i]; }
    const float mean = st * (1.f/1024.f);
    const float var  = qt * (1.f/1024.f) - mean*mean;
    const float rstd = rsqrtf(var + 1e-5f);

    const float4 gv = ((const float4*)g)[tid];
    const float4 bv = ((const float4*)be)[tid];
    float4 o;
    o.x = (x0 - mean) * rstd * gv.x + bv.x;
    o.y = (x1 - mean) * rstd * gv.y + bv.y;
    o.z = (x2 - mean) * rstd * gv.z + bv.z;
    o.w = (x3 - mean) * rstd * gv.w + bv.w;
    ((float4*)(out + (size_t)r*DMODEL))[tid] = o;
    if (DUAL) {
        uint4 u = make_uint4(f2t(o.x), f2t(o.y), f2t(o.z), f2t(o.w));
        ((uint4*)(out_t + (size_t)r*DMODEL))[tid] = u;
    }
}

// ---------------------------------------------------------------------------
#define FLASH_SMEM ((128*68 + 64*68 + 64*72 + 128*68) * 4 + 256*4*2 + 2048)

extern "C" void kernel_launch(void* const* d_in, const int* in_sizes, int n_in,
                              void* d_out, int out_size)
{
    const float* state = (const float*)d_in[0];
    const void*  mask  = d_in[1];
    const float* Wq = (const float*)d_in[2];  const float* bq = (const float*)d_in[3];
    const float* Wk = (const float*)d_in[4];  const float* bk = (const float*)d_in[5];
    const float* Wv = (const float*)d_in[6];  const float* bv = (const float*)d_in[7];
    const float* Wo = (const float*)d_in[8];  const float* bo = (const float*)d_in[9];
    const float* g1 = (const float*)d_in[10]; const float* be1 = (const float*)d_in[11];
    const float* W1 = (const float*)d_in[12]; const float* b1 = (const float*)d_in[13];
    const float* W2 = (const float*)d_in[14]; const float* b2 = (const float*)d_in[15];
    const float* g2 = (const float*)d_in[16]; const float* be2 = (const float*)d_in[17];
    float* out = (float*)d_out;

    unsigned *state_t, *wq_t, *wk_t, *wv_t, *wo_t, *w1_t, *w2_t;
    unsigned *att_t, *x1_t, *h_t;
    float *q, *k, *v, *y, *x1, *y2;
    cudaGetSymbolAddress((void**)&state_t, g_state_t);
    cudaGetSymbolAddress((void**)&wq_t, g_wq_t);
    cudaGetSymbolAddress((void**)&wk_t, g_wk_t);
    cudaGetSymbolAddress((void**)&wv_t, g_wv_t);
    cudaGetSymbolAddress((void**)&wo_t, g_wo_t);
    cudaGetSymbolAddress((void**)&w1_t, g_w1_t);
    cudaGetSymbolAddress((void**)&w2_t, g_w2_t);
    cudaGetSymbolAddress((void**)&q,   g_q);
    cudaGetSymbolAddress((void**)&k,   g_k);
    cudaGetSymbolAddress((void**)&v,   g_v);
    cudaGetSymbolAddress((void**)&att_t, g_att_t);
    cudaGetSymbolAddress((void**)&y,   g_y);
    cudaGetSymbolAddress((void**)&x1,  g_x1);
    cudaGetSymbolAddress((void**)&x1_t, g_x1_t);
    cudaGetSymbolAddress((void**)&h_t, g_h_t);
    cudaGetSymbolAddress((void**)&y2,  g_y2);

    cudaFuncSetAttribute(flash_attn, cudaFuncAttributeMaxDynamicSharedMemorySize,
                         FLASH_SMEM);
    cudaFuncSetAttribute(gemm_tt<false>, cudaFuncAttributeMaxDynamicSharedMemorySize,
                         GEMM_SMEM);
    cudaFuncSetAttribute(gemm_tt<true>, cudaFuncAttributeMaxDynamicSharedMemorySize,
                         GEMM_SMEM);
    cudaFuncSetAttribute(gemm_qkv, cudaFuncAttributeMaxDynamicSharedMemorySize,
                         GEMM_SMEM);

    const dim3 thr(256);
    // converts (state + weights)
    f2t_kernel<<<(NROW*DMODEL/4 + 255)/256, 256>>>(state, state_t, NROW*DMODEL/4);
    f2t_kernel<<<(DMODEL*DMODEL/4 + 255)/256, 256>>>(Wq, wq_t, DMODEL*DMODEL/4);
    f2t_kernel<<<(DMODEL*DMODEL/4 + 255)/256, 256>>>(Wk, wk_t, DMODEL*DMODEL/4);
    f2t_kernel<<<(DMODEL*DMODEL/4 + 255)/256, 256>>>(Wv, wv_t, DMODEL*DMODEL/4);
    f2t_kernel<<<(DMODEL*DMODEL/4 + 255)/256, 256>>>(Wo, wo_t, DMODEL*DMODEL/4);
    f2t_kernel<<<(FFDIM*DMODEL/4 + 255)/256, 256>>>(W1, w1_t, FFDIM*DMODEL/4);
    f2t_kernel<<<(DMODEL*FFDIM/4 + 255)/256, 256>>>(W2, w2_t, DMODEL*FFDIM/4);
    // fused QKV projection (one launch, grid.z = 3)
    gemm_qkv<<<dim3(DMODEL/128, NROW/128, 3), thr, GEMM_SMEM>>>(
        state_t, wq_t, wk_t, wv_t, bq, bk, bv, q, k, v);
    // fused attention -> tf32 output
    flash_attn<<<dim3(SLEN/128, BATCH*NHEAD), thr, FLASH_SMEM>>>(q, k, v, mask, att_t);
    // output projection + LN1 (dual write)
    gemm_tt<false><<<dim3(DMODEL/128, NROW/128), thr, GEMM_SMEM>>>(att_t, wo_t, bo, y, DMODEL, DMODEL);
    add_ln<true><<<NROW, 256>>>(y, state, g1, be1, x1, x1_t);
    // FFN (FF1 writes tf32 with ReLU) + LN2
    gemm_tt<true ><<<dim3(FFDIM/128, NROW/128), thr, GEMM_SMEM>>>(x1_t, w1_t, b1, h_t, FFDIM, DMODEL);
    gemm_tt<false><<<dim3(DMODEL/128, NROW/128), thr, GEMM_SMEM>>>(h_t, w2_t, b2, y2, DMODEL, FFDIM);
    add_ln<false><<<NROW, 256>>>(y2, x1, g2, be2, out, nullptr);
}

// round 11
// speedup vs baseline: 5.9376x; 1.6530x over previous
#include <cuda_runtime.h>
#include <cuda_fp16.h>
#include <math.h>
#include <stdint.h>

#define SLEN 2048
#define BATCH 4
#define DMODEL 1024
#define NHEAD 16
#define HDIM 64
#define FFDIM 4096
#define NROW (SLEN*BATCH)      /* 8192 */
#define LDAQ (BATCH*DMODEL)    /* 4096 */

// ------------------------- static scratch -----------------------------------
__device__ __half g_state_h[NROW*DMODEL];
__device__ __half g_wq_h[DMODEL*DMODEL];
__device__ __half g_wk_h[DMODEL*DMODEL];
__device__ __half g_wv_h[DMODEL*DMODEL];
__device__ __half g_wo_h[DMODEL*DMODEL];
__device__ __half g_w1_h[FFDIM*DMODEL];
__device__ __half g_w2_h[DMODEL*FFDIM];
__device__ __half g_qh [NROW*DMODEL];
__device__ __half g_kh [NROW*DMODEL];
__device__ __half g_vh [NROW*DMODEL];
__device__ __half g_att_h[NROW*DMODEL];
__device__ __half g_x1_h[NROW*DMODEL];
__device__ __half g_hh [NROW*FFDIM];
__device__ float  g_y  [NROW*DMODEL];
__device__ float  g_x1 [NROW*DMODEL];
__device__ float  g_y2 [NROW*DMODEL];

// --------------------------- helpers ----------------------------------------
__device__ __forceinline__ unsigned pk2h(float x, float y) {
    __half2 h = __floats2half2_rn(x, y);
    return *(unsigned*)&h;
}
__device__ __forceinline__ void mma16(float* c, const unsigned* a, unsigned b0, unsigned b1) {
    asm("mma.sync.aligned.m16n8k16.row.col.f32.f16.f16.f32 "
        "{%0,%1,%2,%3},{%4,%5,%6,%7},{%8,%9},{%0,%1,%2,%3};"
        : "+f"(c[0]), "+f"(c[1]), "+f"(c[2]), "+f"(c[3])
        : "r"(a[0]), "r"(a[1]), "r"(a[2]), "r"(a[3]), "r"(b0), "r"(b1));
}
__device__ __forceinline__ void cp16(unsigned dst, const void* src) {
    asm volatile("cp.async.ca.shared.global [%0], [%1], 16;" :: "r"(dst), "l"(src));
}
__device__ __forceinline__ void ldm4(unsigned& r0, unsigned& r1, unsigned& r2, unsigned& r3,
                                     unsigned addr) {
    asm volatile("ldmatrix.sync.aligned.m8n8.x4.shared.b16 {%0,%1,%2,%3}, [%4];"
                 : "=r"(r0), "=r"(r1), "=r"(r2), "=r"(r3) : "r"(addr));
}
__device__ __forceinline__ void ldm4t(unsigned& r0, unsigned& r1, unsigned& r2, unsigned& r3,
                                      unsigned addr) {
    asm volatile("ldmatrix.sync.aligned.m8n8.x4.trans.shared.b16 {%0,%1,%2,%3}, [%4];"
                 : "=r"(r0), "=r"(r1), "=r"(r2), "=r"(r3) : "r"(addr));
}

// fp32 -> fp16 bulk convert (n8 = count of 8-element groups)
__global__ void f2h_kernel(const float* __restrict__ in, __half* __restrict__ out, int n8)
{
    int i = blockIdx.x * blockDim.x + threadIdx.x;
    if (i < n8) {
        const float4* p = (const float4*)in + 2*i;
        float4 a = p[0], b = p[1];
        uint4 o = make_uint4(pk2h(a.x,a.y), pk2h(a.z,a.w), pk2h(b.x,b.y), pk2h(b.z,b.w));
        ((uint4*)out)[i] = o;
    }
}

// ---------------------------------------------------------------------------
// fp16 dense GEMM:  C[M,N] = (A[M,K] * W[N,K]^T + bias) * oscale  (opt ReLU)
// 128x128xBK32 tiles, 4-stage cp.async (80KB dyn smem), m16n8k16, ldmatrix.
// OM: 0 = fp32 out, 1 = fp16 out, 2 = fp16 out + ReLU
// ---------------------------------------------------------------------------
#define GPITCH 40                       /* f16 per smem row */
#define GSLOTB (128*GPITCH*2)           /* bytes per stage per operand */
#define G_SMEM (4*GSLOTB*2)             /* 81920 */

template<int OM>
__device__ __forceinline__
void gemm_h_body(const __half* __restrict__ A, const __half* __restrict__ W,
                 const float* __restrict__ bias, void* __restrict__ Cout,
                 int N, int K, float oscale, void* gsm, int bm, int bn)
{
    const int tid = threadIdx.x;
    const int lane = tid & 31, wid = tid >> 5;
    const int wm = wid >> 2, wn = wid & 3;        // 2 x 4 warp grid, 64x32 tiles
    const int grp = lane >> 2, qd = lane & 3;
    const int row_in = lane & 7, mat = lane >> 3;
    const int r0 = tid >> 1, sg = (tid & 1) * 16;  // load map: row, f16-seg

    const unsigned sa = (unsigned)__cvta_generic_to_shared(gsm);
    const unsigned sb = sa + 4*GSLOTB;

    const __half* Ar = A + (size_t)(bm + r0) * K + sg;
    const __half* Wr = W + (size_t)(bn + r0) * K + sg;
    const unsigned dA = sa + (r0*GPITCH + sg)*2;
    const unsigned dB = sb + (r0*GPITCH + sg)*2;

    const unsigned a_base = (unsigned)(((wm*64 + (mat&1)*8 + row_in)*GPITCH + (mat>>1)*8)*2);
    const unsigned b_base = (unsigned)(((wn*32 + (mat>>1)*8 + row_in)*GPITCH + (mat&1)*8)*2);

    const int ktot = K >> 5;

    float acc[4][4][4];
#pragma unroll
    for (int i = 0; i < 4; i++)
#pragma unroll
        for (int j = 0; j < 4; j++)
#pragma unroll
            for (int x = 0; x < 4; x++) acc[i][j][x] = 0.f;

#pragma unroll
    for (int p = 0; p < 3; p++) {
        const unsigned off = p * GSLOTB;
        cp16(dA + off,      Ar + p*32);
        cp16(dA + off + 16, Ar + p*32 + 8);
        cp16(dB + off,      Wr + p*32);
        cp16(dB + off + 16, Wr + p*32 + 8);
        asm volatile("cp.async.commit_group;" ::: "memory");
    }

    for (int kt = 0; kt < ktot; kt++) {
        asm volatile("cp.async.wait_group 2;" ::: "memory");
        __syncthreads();
        const int nk = kt + 3;
        if (nk < ktot) {
            const unsigned off = (nk & 3) * GSLOTB;
            cp16(dA + off,      Ar + nk*32);
            cp16(dA + off + 16, Ar + nk*32 + 8);
            cp16(dB + off,      Wr + nk*32);
            cp16(dB + off + 16, Wr + nk*32 + 8);
        }
        asm volatile("cp.async.commit_group;" ::: "memory");

        const unsigned slA = sa + (kt & 3) * GSLOTB;
        const unsigned slB = sb + (kt & 3) * GSLOTB;
#pragma unroll
        for (int kk = 0; kk < 32; kk += 16) {
            unsigned a[4][4], b[4][2];
#pragma unroll
            for (int mi = 0; mi < 4; mi++)
                ldm4(a[mi][0], a[mi][1], a[mi][2], a[mi][3],
                     slA + a_base + (unsigned)(mi*16*GPITCH*2 + kk*2));
#pragma unroll
            for (int h2 = 0; h2 < 2; h2++) {
                unsigned q0, q1, q2, q3;
                ldm4(q0, q1, q2, q3,
                     slB + b_base + (unsigned)(h2*16*GPITCH*2 + kk*2));
                b[2*h2][0] = q0; b[2*h2][1] = q1;
                b[2*h2+1][0] = q2; b[2*h2+1][1] = q3;
            }
#pragma unroll
            for (int mi = 0; mi < 4; mi++)
#pragma unroll
                for (int ni = 0; ni < 4; ni++)
                    mma16(acc[mi][ni], a[mi], b[ni][0], b[ni][1]);
        }
    }

#pragma unroll
    for (int mi = 0; mi < 4; mi++) {
        const int row = bm + wm*64 + mi*16 + grp;
#pragma unroll
        for (int ni = 0; ni < 4; ni++) {
            const int col = bn + wn*32 + ni*8 + qd*2;
            float g0 = bias[col], g1 = bias[col+1];
            float o0 = (acc[mi][ni][0] + g0) * oscale;
            float o1 = (acc[mi][ni][1] + g1) * oscale;
            float o2 = (acc[mi][ni][2] + g0) * oscale;
            float o3 = (acc[mi][ni][3] + g1) * oscale;
            if (OM == 2) { o0=fmaxf(o0,0.f); o1=fmaxf(o1,0.f); o2=fmaxf(o2,0.f); o3=fmaxf(o3,0.f); }
            if (OM == 0) {
                float* Cf = (float*)Cout;
                *(float2*)(Cf + (size_t)row    * N + col) = make_float2(o0, o1);
                *(float2*)(Cf + (size_t)(row+8)* N + col) = make_float2(o2, o3);
            } else {
                __half* Ch = (__half*)Cout;
                *(unsigned*)(Ch + (size_t)row    * N + col) = pk2h(o0, o1);
                *(unsigned*)(Ch + (size_t)(row+8)* N + col) = pk2h(o2, o3);
            }
        }
    }
}

template<int OM>
__global__ __launch_bounds__(256, 2)
void gemm_h(const __half* __restrict__ A, const __half* __restrict__ W,
            const float* __restrict__ bias, void* __restrict__ Cout, int N, int K)
{
    extern __shared__ char gsm[];
    gemm_h_body<OM>(A, W, bias, Cout, N, K, 1.f, gsm, blockIdx.y*128, blockIdx.x*128);
}

// fused QKV: blockIdx.z selects weight/bias/output; q gets 0.125 scale
__global__ __launch_bounds__(256, 2)
void gemm_qkv_h(const __half* __restrict__ A,
                const __half* __restrict__ Wq, const __half* __restrict__ Wk,
                const __half* __restrict__ Wv,
                const float* __restrict__ bq, const float* __restrict__ bk,
                const float* __restrict__ bv,
                __half* __restrict__ Cq, __half* __restrict__ Ck, __half* __restrict__ Cv)
{
    extern __shared__ char gsm2[];
    const int z = blockIdx.z;
    const __half* W = (z == 0) ? Wq : (z == 1) ? Wk : Wv;
    const float* bias = (z == 0) ? bq : (z == 1) ? bk : bv;
    __half* C         = (z == 0) ? Cq : (z == 1) ? Ck : Cv;
    const float sc    = (z == 0) ? 0.125f : 1.f;
    gemm_h_body<1>(A, W, bias, C, DMODEL, DMODEL, sc, gsm2, blockIdx.y*128, blockIdx.x*128);
}

// ---------------------------------------------------------------------------
// Fused flash attention, fp16 operands, m16n8k16, cp.async tile loads.
// Q pre-scaled by 1/8 at QKV epilogue. Output fp16 [s*B+b, h*64+d].
// ---------------------------------------------------------------------------
#define FLASH_SMEM ((128*72 + 64*72 + 64*72 + 128*72)*2 + 256*4*2 + 2048)

__global__ __launch_bounds__(256, 2)
void flash_attn_h(const __half* __restrict__ Q, const __half* __restrict__ K,
                  const __half* __restrict__ V, const void* __restrict__ mask,
                  __half* __restrict__ O)
{
    extern __shared__ __half sm_h[];
    __half* Qs = sm_h;                  // 128*72
    __half* Ks = Qs + 128*72;           // 64*72
    __half* Vs = Ks + 64*72;            // 64*72
    __half* Ps = Vs + 64*72;            // 128*72
    float* redm = (float*)(Ps + 128*72);  // 256
    float* redl = redm + 256;             // 256
    unsigned char* msk = (unsigned char*)(redl + 256);  // 2048
    __shared__ int s_end;

    const int tid = threadIdx.x, lane = tid & 31, wid = tid >> 5;
    const int wm = wid >> 1, wn = wid & 1;       // 4 x 2 warps, 32x32 tiles
    const int grp = lane >> 2, qd = lane & 3;
    const int row_in = lane & 7, mat = lane >> 3;
    const int bh = blockIdx.y, b = bh >> 4, h = bh & 15;
    const int bm = blockIdx.x * 128;

    const __half* qb = Q + b*DMODEL + h*HDIM;
    const __half* kb = K + b*DMODEL + h*HDIM;
    const __half* vb = V + b*DMODEL + h*HDIM;

    const unsigned sQ = (unsigned)__cvta_generic_to_shared(Qs);
    const unsigned sK = (unsigned)__cvta_generic_to_shared(Ks);
    const unsigned sV = (unsigned)__cvta_generic_to_shared(Vs);
    const unsigned sP = (unsigned)__cvta_generic_to_shared(Ps);

    const unsigned aqb = (unsigned)(((wm*32 + (mat&1)*8 + row_in)*72 + (mat>>1)*8)*2);
    const unsigned bkb = (unsigned)(((wn*32 + (mat>>1)*8 + row_in)*72 + (mat&1)*8)*2);
    const unsigned vtb = (unsigned)((((mat&1)*8 + row_in)*72 + wn*32 + (mat>>1)*8)*2);

    if (tid == 0) s_end = SLEN;
    // Q tile -> smem via cp.async (already scaled by 1/8 at QKV epilogue)
    {
        const int r = tid >> 1, sg = (tid & 1) * 32;
        const __half* src = qb + (size_t)(bm + r) * LDAQ + sg;
        const unsigned dst = sQ + (unsigned)((r*72 + sg)*2);
        cp16(dst,      src);
        cp16(dst + 16, src + 8);
        cp16(dst + 32, src + 16);
        cp16(dst + 48, src + 24);
        asm volatile("cp.async.commit_group;" ::: "memory");
    }
    // mask row -> smem (u8-bool or int32 probed at runtime)
    {
        const unsigned char* m8  = (const unsigned char*)mask;
        const int*           m32 = (const int*)mask;
        const bool isu8 = (m8[SLEN - 1] == 1);
        for (int t = tid; t < SLEN; t += 256)
            msk[t] = isu8 ? (m8[(size_t)b*SLEN + t] != 0)
                          : (m32[(size_t)b*SLEN + t] != 0);
    }
    asm volatile("cp.async.wait_group 0;" ::: "memory");
    __syncthreads();
    {
        int lm = SLEN;
        for (int t = tid; t < SLEN; t += 256)
            if (msk[t]) { lm = t; break; }
        if (lm < SLEN) atomicMin(&s_end, lm);
    }
    __syncthreads();
    const int kv_end = min(SLEN, (s_end + 63) & ~63);

    float m_st[2][2], l_st[2][2];
    float oacc[2][4][4];
#pragma unroll
    for (int mi = 0; mi < 2; mi++) {
        m_st[mi][0] = -INFINITY; m_st[mi][1] = -INFINITY;
        l_st[mi][0] = 0.f;       l_st[mi][1] = 0.f;
#pragma unroll
        for (int ni = 0; ni < 4; ni++)
#pragma unroll
            for (int x = 0; x < 4; x++) oacc[mi][ni][x] = 0.f;
    }

    const int rkv = tid >> 2, skv = (tid & 3) * 16;

    for (int kt = 0; kt < kv_end; kt += 64) {
        __syncthreads();   // prev-iter reads of Ks/Vs complete
        {
            const __half* ks = kb + (size_t)(kt + rkv) * LDAQ + skv;
            const __half* vs = vb + (size_t)(kt + rkv) * LDAQ + skv;
            const unsigned dk = sK + (unsigned)((rkv*72 + skv)*2);
            const unsigned dv = sV + (unsigned)((rkv*72 + skv)*2);
            cp16(dk,      ks); cp16(dk + 16, ks + 8);
            cp16(dv,      vs); cp16(dv + 16, vs + 8);
            asm volatile("cp.async.commit_group;" ::: "memory");
            asm volatile("cp.async.wait_group 0;" ::: "memory");
        }
        __syncthreads();

        // S = Q * K^T
        float sacc[2][4][4];
#pragma unroll
        for (int mi = 0; mi < 2; mi++)
#pragma unroll
            for (int ni = 0; ni < 4; ni++)
#pragma unroll
                for (int x = 0; x < 4; x++) sacc[mi][ni][x] = 0.f;
#pragma unroll
        for (int kk = 0; kk < 64; kk += 16) {
            unsigned a[2][4], bb[4][2];
#pragma unroll
            for (int mi = 0; mi < 2; mi++)
                ldm4(a[mi][0], a[mi][1], a[mi][2], a[mi][3],
                     sQ + aqb + (unsigned)(mi*16*72*2 + kk*2));
#pragma unroll
            for (int h2 = 0; h2 < 2; h2++) {
                unsigned q0, q1, q2, q3;
                ldm4(q0, q1, q2, q3, sK + bkb + (unsigned)(h2*16*72*2 + kk*2));
                bb[2*h2][0] = q0; bb[2*h2][1] = q1;
                bb[2*h2+1][0] = q2; bb[2*h2+1][1] = q3;
            }
#pragma unroll
            for (int mi = 0; mi < 2; mi++)
#pragma unroll
                for (int ni = 0; ni < 4; ni++)
                    mma16(sacc[mi][ni], a[mi], bb[ni][0], bb[ni][1]);
        }
        // mask
#pragma unroll
        for (int ni = 0; ni < 4; ni++) {
            const int c0 = kt + wn*32 + ni*8 + qd*2;
            if (msk[c0]) {
                sacc[0][ni][0] = -INFINITY; sacc[0][ni][2] = -INFINITY;
                sacc[1][ni][0] = -INFINITY; sacc[1][ni][2] = -INFINITY;
            }
            if (msk[c0+1]) {
                sacc[0][ni][1] = -INFINITY; sacc[0][ni][3] = -INFINITY;
                sacc[1][ni][1] = -INFINITY; sacc[1][ni][3] = -INFINITY;
            }
        }
        // row max
#pragma unroll
        for (int mi = 0; mi < 2; mi++)
#pragma unroll
            for (int hf = 0; hf < 2; hf++) {
                float mx = -INFINITY;
#pragma unroll
                for (int ni = 0; ni < 4; ni++)
                    mx = fmaxf(mx, fmaxf(sacc[mi][ni][hf*2], sacc[mi][ni][hf*2+1]));
                mx = fmaxf(mx, __shfl_xor_sync(0xffffffffu, mx, 1));
                mx = fmaxf(mx, __shfl_xor_sync(0xffffffffu, mx, 2));
                if (qd == 0) redm[wn*128 + wm*32 + mi*16 + hf*8 + grp] = mx;
            }
        __syncthreads();

        float sc[2][2];
#pragma unroll
        for (int mi = 0; mi < 2; mi++)
#pragma unroll
            for (int hf = 0; hf < 2; hf++) {
                const int row = wm*32 + mi*16 + hf*8 + grp;
                const float tm = fmaxf(redm[row], redm[128 + row]);
                const float mnew = fmaxf(m_st[mi][hf], tm);
                sc[mi][hf] = __expf(m_st[mi][hf] - mnew);
                m_st[mi][hf] = mnew;
            }
        float ls[2][2] = {{0.f,0.f},{0.f,0.f}};
#pragma unroll
        for (int mi = 0; mi < 2; mi++) {
            const int r = wm*32 + mi*16 + grp;
#pragma unroll
            for (int ni = 0; ni < 4; ni++) {
                const int c = wn*32 + ni*8 + qd*2;
                float p0 = __expf(sacc[mi][ni][0] - m_st[mi][0]);
                float p1 = __expf(sacc[mi][ni][1] - m_st[mi][0]);
                float p2 = __expf(sacc[mi][ni][2] - m_st[mi][1]);
                float p3 = __expf(sacc[mi][ni][3] - m_st[mi][1]);
                ls[mi][0] += p0 + p1;
                ls[mi][1] += p2 + p3;
                *(unsigned*)(Ps + r*72 + c)     = pk2h(p0, p1);
                *(unsigned*)(Ps + (r+8)*72 + c) = pk2h(p2, p3);
            }
        }
#pragma unroll
        for (int mi = 0; mi < 2; mi++)
#pragma unroll
            for (int hf = 0; hf < 2; hf++) {
                float s = ls[mi][hf];
                s += __shfl_xor_sync(0xffffffffu, s, 1);
                s += __shfl_xor_sync(0xffffffffu, s, 2);
                if (qd == 0) redl[wn*128 + wm*32 + mi*16 + hf*8 + grp] = s;
            }
        __syncthreads();
#pragma unroll
        for (int mi = 0; mi < 2; mi++)
#pragma unroll
            for (int hf = 0; hf < 2; hf++) {
                const int row = wm*32 + mi*16 + hf*8 + grp;
                l_st[mi][hf] = l_st[mi][hf] * sc[mi][hf] + redl[row] + redl[128 + row];
            }
#pragma unroll
        for (int mi = 0; mi < 2; mi++)
#pragma unroll
            for (int ni = 0; ni < 4; ni++) {
                oacc[mi][ni][0] *= sc[mi][0]; oacc[mi][ni][1] *= sc[mi][0];
                oacc[mi][ni][2] *= sc[mi][1]; oacc[mi][ni][3] *= sc[mi][1];
            }
        // O += P * V   (V via ldmatrix.trans)
#pragma unroll
        for (int kk = 0; kk < 64; kk += 16) {
            unsigned a[2][4], bb[4][2];
#pragma unroll
            for (int mi = 0; mi < 2; mi++)
                ldm4(a[mi][0], a[mi][1], a[mi][2], a[mi][3],
                     sP + aqb + (unsigned)(mi*16*72*2 + kk*2));
#pragma unroll
            for (int j2 = 0; j2 < 2; j2++) {
                unsigned q0, q1, q2, q3;
                ldm4t(q0, q1, q2, q3, sV + vtb + (unsigned)(kk*72*2 + j2*32));
                bb[2*j2][0] = q0; bb[2*j2][1] = q1;
                bb[2*j2+1][0] = q2; bb[2*j2+1][1] = q3;
            }
#pragma unroll
            for (int mi = 0; mi < 2; mi++)
#pragma unroll
                for (int ni = 0; ni < 4; ni++)
                    mma16(oacc[mi][ni], a[mi], bb[ni][0], bb[ni][1]);
        }
    }

    // epilogue: O = fp16(O / l)
#pragma unroll
    for (int mi = 0; mi < 2; mi++) {
        const int s0 = bm + wm*32 + mi*16 + grp;
        const float inv0 = 1.f / l_st[mi][0];
        const float inv1 = 1.f / l_st[mi][1];
#pragma unroll
        for (int ni = 0; ni < 4; ni++) {
            const int c = h*HDIM + wn*32 + ni*8 + qd*2;
            __half* o0 = O + ((size_t)s0     * BATCH + b) * DMODEL + c;
            __half* o1 = O + ((size_t)(s0+8) * BATCH + b) * DMODEL + c;
            *(unsigned*)o0 = pk2h(oacc[mi][ni][0]*inv0, oacc[mi][ni][1]*inv0);
            *(unsigned*)o1 = pk2h(oacc[mi][ni][2]*inv1, oacc[mi][ni][3]*inv1);
        }
    }
}

// ---------------------------------------------------------------------------
// out = LayerNorm(y + res) * g + b; optionally also writes fp16 copy.
// ---------------------------------------------------------------------------
template<bool DUAL>
__global__ void add_ln(const float* __restrict__ y, const float* __restrict__ res,
                       const float* __restrict__ g, const float* __restrict__ be,
                       float* __restrict__ out, __half* __restrict__ out_h)
{
    const int r   = blockIdx.x;
    const int tid = threadIdx.x;
    const float4 a  = ((const float4*)(y   + (size_t)r*DMODEL))[tid];
    const float4 b4 = ((const float4*)(res + (size_t)r*DMODEL))[tid];
    float x0 = a.x + b4.x, x1 = a.y + b4.y, x2 = a.z + b4.z, x3 = a.w + b4.w;
    float s = x0 + x1 + x2 + x3;
    float q = x0*x0 + x1*x1 + x2*x2 + x3*x3;

    __shared__ float rs[8], rq[8];
#pragma unroll
    for (int o = 16; o; o >>= 1) {
        s += __shfl_xor_sync(0xffffffffu, s, o);
        q += __shfl_xor_sync(0xffffffffu, q, o);
    }
    if ((tid & 31) == 0) { rs[tid >> 5] = s; rq[tid >> 5] = q; }
    __syncthreads();
    float st = 0.f, qt = 0.f;
#pragma unroll
    for (int i = 0; i < 8; i++) { st += rs[i]; qt += rq[i]; }
    const float mean = st * (1.f/1024.f);
    const float var  = qt * (1.f/1024.f) - mean*mean;
    const float rstd = rsqrtf(var + 1e-5f);

    const float4 gv = ((const float4*)g)[tid];
    const float4 bv = ((const float4*)be)[tid];
    float4 o;
    o.x = (x0 - mean) * rstd * gv.x + bv.x;
    o.y = (x1 - mean) * rstd * gv.y + bv.y;
    o.z = (x2 - mean) * rstd * gv.z + bv.z;
    o.w = (x3 - mean) * rstd * gv.w + bv.w;
    ((float4*)(out + (size_t)r*DMODEL))[tid] = o;
    if (DUAL) {
        uint2 u = make_uint2(pk2h(o.x, o.y), pk2h(o.z, o.w));
        ((uint2*)(out_h + (size_t)r*DMODEL))[tid] = u;
    }
}

// ---------------------------------------------------------------------------
extern "C" void kernel_launch(void* const* d_in, const int* in_sizes, int n_in,
                              void* d_out, int out_size)
{
    const float* state = (const float*)d_in[0];
    const void*  mask  = d_in[1];
    const float* Wq = (const float*)d_in[2];  const float* bq = (const float*)d_in[3];
    const float* Wk = (const float*)d_in[4];  const float* bk = (const float*)d_in[5];
    const float* Wv = (const float*)d_in[6];  const float* bv = (const float*)d_in[7];
    const float* Wo = (const float*)d_in[8];  const float* bo = (const float*)d_in[9];
    const float* g1 = (const float*)d_in[10]; const float* be1 = (const float*)d_in[11];
    const float* W1 = (const float*)d_in[12]; const float* b1 = (const float*)d_in[13];
    const float* W2 = (const float*)d_in[14]; const float* b2 = (const float*)d_in[15];
    const float* g2 = (const float*)d_in[16]; const float* be2 = (const float*)d_in[17];
    float* out = (float*)d_out;

    __half *state_h, *wq_h, *wk_h, *wv_h, *wo_h, *w1_h, *w2_h;
    __half *qh, *kh, *vh, *att_h, *x1_h, *hh;
    float *y, *x1, *y2;
    cudaGetSymbolAddress((void**)&state_h, g_state_h);
    cudaGetSymbolAddress((void**)&wq_h, g_wq_h);
    cudaGetSymbolAddress((void**)&wk_h, g_wk_h);
    cudaGetSymbolAddress((void**)&wv_h, g_wv_h);
    cudaGetSymbolAddress((void**)&wo_h, g_wo_h);
    cudaGetSymbolAddress((void**)&w1_h, g_w1_h);
    cudaGetSymbolAddress((void**)&w2_h, g_w2_h);
    cudaGetSymbolAddress((void**)&qh,  g_qh);
    cudaGetSymbolAddress((void**)&kh,  g_kh);
    cudaGetSymbolAddress((void**)&vh,  g_vh);
    cudaGetSymbolAddress((void**)&att_h, g_att_h);
    cudaGetSymbolAddress((void**)&x1_h, g_x1_h);
    cudaGetSymbolAddress((void**)&hh,  g_hh);
    cudaGetSymbolAddress((void**)&y,   g_y);
    cudaGetSymbolAddress((void**)&x1,  g_x1);
    cudaGetSymbolAddress((void**)&y2,  g_y2);

    cudaFuncSetAttribute(flash_attn_h, cudaFuncAttributeMaxDynamicSharedMemorySize,
                         FLASH_SMEM);
    cudaFuncSetAttribute(gemm_h<0>, cudaFuncAttributeMaxDynamicSharedMemorySize, G_SMEM);
    cudaFuncSetAttribute(gemm_h<1>, cudaFuncAttributeMaxDynamicSharedMemorySize, G_SMEM);
    cudaFuncSetAttribute(gemm_h<2>, cudaFuncAttributeMaxDynamicSharedMemorySize, G_SMEM);
    cudaFuncSetAttribute(gemm_qkv_h, cudaFuncAttributeMaxDynamicSharedMemorySize, G_SMEM);

    // converts (state + weights) to fp16
    f2h_kernel<<<(NROW*DMODEL/8 + 255)/256, 256>>>(state, state_h, NROW*DMODEL/8);
    f2h_kernel<<<(DMODEL*DMODEL/8 + 255)/256, 256>>>(Wq, wq_h, DMODEL*DMODEL/8);
    f2h_kernel<<<(DMODEL*DMODEL/8 + 255)/256, 256>>>(Wk, wk_h, DMODEL*DMODEL/8);
    f2h_kernel<<<(DMODEL*DMODEL/8 + 255)/256, 256>>>(Wv, wv_h, DMODEL*DMODEL/8);
    f2h_kernel<<<(DMODEL*DMODEL/8 + 255)/256, 256>>>(Wo, wo_h, DMODEL*DMODEL/8);
    f2h_kernel<<<(FFDIM*DMODEL/8 + 255)/256, 256>>>(W1, w1_h, FFDIM*DMODEL/8);
    f2h_kernel<<<(DMODEL*FFDIM/8 + 255)/256, 256>>>(W2, w2_h, DMODEL*FFDIM/8);
    // fused QKV projection (fp16 out; q pre-scaled by 1/8)
    gemm_qkv_h<<<dim3(DMODEL/128, NROW/128, 3), 256, G_SMEM>>>(
        state_h, wq_h, wk_h, wv_h, bq, bk, bv, qh, kh, vh);
    // fused attention -> fp16 output
    flash_attn_h<<<dim3(SLEN/128, BATCH*NHEAD), 256, FLASH_SMEM>>>(qh, kh, vh, mask, att_h);
    // output projection + LN1 (dual write)
    gemm_h<0><<<dim3(DMODEL/128, NROW/128), 256, G_SMEM>>>(att_h, wo_h, bo, y, DMODEL, DMODEL);
    add_ln<true><<<NROW, 256>>>(y, state, g1, be1, x1, x1_h);
    // FFN (FF1 fp16+ReLU) + LN2
    gemm_h<2><<<dim3(FFDIM/128, NROW/128), 256, G_SMEM>>>(x1_h, w1_h, b1, hh, FFDIM, DMODEL);
    gemm_h<0><<<dim3(DMODEL/128, NROW/128), 256, G_SMEM>>>(hh, w2_h, b2, y2, DMODEL, FFDIM);
    add_ln<false><<<NROW, 256>>>(y2, x1, g2, be2, out, nullptr);
}

// round 12
// speedup vs baseline: 6.0426x; 1.0177x over previous
#include <cuda_runtime.h>
#include <cuda_fp16.h>
#include <math.h>
#include <stdint.h>

#define SLEN 2048
#define BATCH 4
#define DMODEL 1024
#define NHEAD 16
#define HDIM 64
#define FFDIM 4096
#define NROW (SLEN*BATCH)      /* 8192 */
#define LDAQ (BATCH*DMODEL)    /* 4096 */

// ------------------------- static scratch -----------------------------------
__device__ __half g_state_h[NROW*DMODEL];
__device__ __half g_wq_h[DMODEL*DMODEL];
__device__ __half g_wk_h[DMODEL*DMODEL];
__device__ __half g_wv_h[DMODEL*DMODEL];
__device__ __half g_wo_h[DMODEL*DMODEL];
__device__ __half g_w1_h[FFDIM*DMODEL];
__device__ __half g_w2_h[DMODEL*FFDIM];
__device__ __half g_qh [NROW*DMODEL];
__device__ __half g_kh [NROW*DMODEL];
__device__ __half g_vh [NROW*DMODEL];
__device__ __half g_att_h[NROW*DMODEL];
__device__ __half g_x1_h[NROW*DMODEL];
__device__ __half g_hh [NROW*FFDIM];
__device__ float  g_y  [NROW*DMODEL];
__device__ float  g_x1 [NROW*DMODEL];
__device__ float  g_y2 [NROW*DMODEL];

// --------------------------- helpers ----------------------------------------
__device__ __forceinline__ unsigned pk2h(float x, float y) {
    __half2 h = __floats2half2_rn(x, y);
    return *(unsigned*)&h;
}
__device__ __forceinline__ void mma16(float* c, const unsigned* a, unsigned b0, unsigned b1) {
    asm("mma.sync.aligned.m16n8k16.row.col.f32.f16.f16.f32 "
        "{%0,%1,%2,%3},{%4,%5,%6,%7},{%8,%9},{%0,%1,%2,%3};"
        : "+f"(c[0]), "+f"(c[1]), "+f"(c[2]), "+f"(c[3])
        : "r"(a[0]), "r"(a[1]), "r"(a[2]), "r"(a[3]), "r"(b0), "r"(b1));
}
__device__ __forceinline__ void cp16(unsigned dst, const void* src) {
    asm volatile("cp.async.ca.shared.global [%0], [%1], 16;" :: "r"(dst), "l"(src));
}
__device__ __forceinline__ void ldm4(unsigned& r0, unsigned& r1, unsigned& r2, unsigned& r3,
                                     unsigned addr) {
    asm volatile("ldmatrix.sync.aligned.m8n8.x4.shared.b16 {%0,%1,%2,%3}, [%4];"
                 : "=r"(r0), "=r"(r1), "=r"(r2), "=r"(r3) : "r"(addr));
}
__device__ __forceinline__ void ldm4t(unsigned& r0, unsigned& r1, unsigned& r2, unsigned& r3,
                                      unsigned addr) {
    asm volatile("ldmatrix.sync.aligned.m8n8.x4.trans.shared.b16 {%0,%1,%2,%3}, [%4];"
                 : "=r"(r0), "=r"(r1), "=r"(r2), "=r"(r3) : "r"(addr));
}

// single-launch fp32 -> fp16 convert of all 7 tensors (grid.z selects segment)
__global__ void f2h_all(const float* s,  __half* so,
                        const float* w0, __half* o0, const float* w1, __half* o1,
                        const float* w2, __half* o2, const float* w3, __half* o3,
                        const float* w4, __half* o4, const float* w5, __half* o5)
{
    const int z = blockIdx.z;
    const float* in; __half* out; int n8;
    switch (z) {
        case 0: in = s;  out = so; n8 = NROW*DMODEL/8;   break;
        case 1: in = w0; out = o0; n8 = DMODEL*DMODEL/8; break;
        case 2: in = w1; out = o1; n8 = DMODEL*DMODEL/8; break;
        case 3: in = w2; out = o2; n8 = DMODEL*DMODEL/8; break;
        case 4: in = w3; out = o3; n8 = DMODEL*DMODEL/8; break;
        case 5: in = w4; out = o4; n8 = FFDIM*DMODEL/8;  break;
        default:in = w5; out = o5; n8 = DMODEL*FFDIM/8;  break;
    }
    int i = blockIdx.x * blockDim.x + threadIdx.x;
    if (i < n8) {
        const float4* p = (const float4*)in + 2*i;
        float4 a = p[0], b = p[1];
        uint4 o = make_uint4(pk2h(a.x,a.y), pk2h(a.z,a.w), pk2h(b.x,b.y), pk2h(b.z,b.w));
        ((uint4*)out)[i] = o;
    }
}

// ---------------------------------------------------------------------------
// fp16 dense GEMM:  C[M,N] = (A[M,K] * W[N,K]^T + bias) * oscale  (opt ReLU)
// 128x128xBK32 tiles, 4-stage cp.async (80KB dyn smem), m16n8k16, ldmatrix.
// OM: 0 = fp32 out, 1 = fp16 out, 2 = fp16 out + ReLU
// ---------------------------------------------------------------------------
#define GPITCH 40                       /* f16 per smem row */
#define GSLOTB (128*GPITCH*2)           /* bytes per stage per operand */
#define G_SMEM (4*GSLOTB*2)             /* 81920 */

template<int OM>
__device__ __forceinline__
void gemm_h_body(const __half* __restrict__ A, const __half* __restrict__ W,
                 const float* __restrict__ bias, void* __restrict__ Cout,
                 int N, int K, float oscale, void* gsm, int bm, int bn)
{
    const int tid = threadIdx.x;
    const int lane = tid & 31, wid = tid >> 5;
    const int wm = wid >> 2, wn = wid & 3;        // 2 x 4 warp grid, 64x32 tiles
    const int grp = lane >> 2, qd = lane & 3;
    const int row_in = lane & 7, mat = lane >> 3;
    const int r0 = tid >> 1, sg = (tid & 1) * 16;

    const unsigned sa = (unsigned)__cvta_generic_to_shared(gsm);
    const unsigned sb = sa + 4*GSLOTB;

    const __half* Ar = A + (size_t)(bm + r0) * K + sg;
    const __half* Wr = W + (size_t)(bn + r0) * K + sg;
    const unsigned dA = sa + (r0*GPITCH + sg)*2;
    const unsigned dB = sb + (r0*GPITCH + sg)*2;

    const unsigned a_base = (unsigned)(((wm*64 + (mat&1)*8 + row_in)*GPITCH + (mat>>1)*8)*2);
    const unsigned b_base = (unsigned)(((wn*32 + (mat>>1)*8 + row_in)*GPITCH + (mat&1)*8)*2);

    const int ktot = K >> 5;

    float acc[4][4][4];
#pragma unroll
    for (int i = 0; i < 4; i++)
#pragma unroll
        for (int j = 0; j < 4; j++)
#pragma unroll
            for (int x = 0; x < 4; x++) acc[i][j][x] = 0.f;

#pragma unroll
    for (int p = 0; p < 3; p++) {
        const unsigned off = p * GSLOTB;
        cp16(dA + off,      Ar + p*32);
        cp16(dA + off + 16, Ar + p*32 + 8);
        cp16(dB + off,      Wr + p*32);
        cp16(dB + off + 16, Wr + p*32 + 8);
        asm volatile("cp.async.commit_group;" ::: "memory");
    }

    for (int kt = 0; kt < ktot; kt++) {
        asm volatile("cp.async.wait_group 2;" ::: "memory");
        __syncthreads();
        const int nk = kt + 3;
        if (nk < ktot) {
            const unsigned off = (nk & 3) * GSLOTB;
            cp16(dA + off,      Ar + nk*32);
            cp16(dA + off + 16, Ar + nk*32 + 8);
            cp16(dB + off,      Wr + nk*32);
            cp16(dB + off + 16, Wr + nk*32 + 8);
        }
        asm volatile("cp.async.commit_group;" ::: "memory");

        const unsigned slA = sa + (kt & 3) * GSLOTB;
        const unsigned slB = sb + (kt & 3) * GSLOTB;
#pragma unroll
        for (int kk = 0; kk < 32; kk += 16) {
            unsigned a[4][4], b[4][2];
#pragma unroll
            for (int mi = 0; mi < 4; mi++)
                ldm4(a[mi][0], a[mi][1], a[mi][2], a[mi][3],
                     slA + a_base + (unsigned)(mi*16*GPITCH*2 + kk*2));
#pragma unroll
            for (int h2 = 0; h2 < 2; h2++) {
                unsigned q0, q1, q2, q3;
                ldm4(q0, q1, q2, q3,
                     slB + b_base + (unsigned)(h2*16*GPITCH*2 + kk*2));
                b[2*h2][0] = q0; b[2*h2][1] = q1;
                b[2*h2+1][0] = q2; b[2*h2+1][1] = q3;
            }
#pragma unroll
            for (int mi = 0; mi < 4; mi++)
#pragma unroll
                for (int ni = 0; ni < 4; ni++)
                    mma16(acc[mi][ni], a[mi], b[ni][0], b[ni][1]);
        }
    }

#pragma unroll
    for (int mi = 0; mi < 4; mi++) {
        const int row = bm + wm*64 + mi*16 + grp;
#pragma unroll
        for (int ni = 0; ni < 4; ni++) {
            const int col = bn + wn*32 + ni*8 + qd*2;
            float g0 = bias[col], g1 = bias[col+1];
            float o0 = (acc[mi][ni][0] + g0) * oscale;
            float o1 = (acc[mi][ni][1] + g1) * oscale;
            float o2 = (acc[mi][ni][2] + g0) * oscale;
            float o3 = (acc[mi][ni][3] + g1) * oscale;
            if (OM == 2) { o0=fmaxf(o0,0.f); o1=fmaxf(o1,0.f); o2=fmaxf(o2,0.f); o3=fmaxf(o3,0.f); }
            if (OM == 0) {
                float* Cf = (float*)Cout;
                *(float2*)(Cf + (size_t)row    * N + col) = make_float2(o0, o1);
                *(float2*)(Cf + (size_t)(row+8)* N + col) = make_float2(o2, o3);
            } else {
                __half* Ch = (__half*)Cout;
                *(unsigned*)(Ch + (size_t)row    * N + col) = pk2h(o0, o1);
                *(unsigned*)(Ch + (size_t)(row+8)* N + col) = pk2h(o2, o3);
            }
        }
    }
}

template<int OM>
__global__ __launch_bounds__(256, 2)
void gemm_h(const __half* __restrict__ A, const __half* __restrict__ W,
            const float* __restrict__ bias, void* __restrict__ Cout, int N, int K)
{
    extern __shared__ char gsm[];
    gemm_h_body<OM>(A, W, bias, Cout, N, K, 1.f, gsm, blockIdx.y*128, blockIdx.x*128);
}

// fused QKV: blockIdx.z selects weight/bias/output; q gets 0.125 scale
__global__ __launch_bounds__(256, 2)
void gemm_qkv_h(const __half* __restrict__ A,
                const __half* __restrict__ Wq, const __half* __restrict__ Wk,
                const __half* __restrict__ Wv,
                const float* __restrict__ bq, const float* __restrict__ bk,
                const float* __restrict__ bv,
                __half* __restrict__ Cq, __half* __restrict__ Ck, __half* __restrict__ Cv)
{
    extern __shared__ char gsm2[];
    const int z = blockIdx.z;
    const __half* W = (z == 0) ? Wq : (z == 1) ? Wk : Wv;
    const float* bias = (z == 0) ? bq : (z == 1) ? bk : bv;
    __half* C         = (z == 0) ? Cq : (z == 1) ? Ck : Cv;
    const float sc    = (z == 0) ? 0.125f : 1.f;
    gemm_h_body<1>(A, W, bias, C, DMODEL, DMODEL, sc, gsm2, blockIdx.y*128, blockIdx.x*128);
}

// ---------------------------------------------------------------------------
// Fused flash attention, fp16, m16n8k16, double-buffered K/V via cp.async.
// Q pre-scaled by 1/8 at QKV epilogue. Output fp16 [s*B+b, h*64+d].
// ---------------------------------------------------------------------------
#define KVSTAGE_B (64*72*2)     /* bytes per K (or V) stage */
#define FLASH_SMEM ((128*72 + 2*64*72 + 2*64*72 + 128*72)*2 + 256*4*2 + 2048)

__global__ __launch_bounds__(256, 2)
void flash_attn_h(const __half* __restrict__ Q, const __half* __restrict__ K,
                  const __half* __restrict__ V, const void* __restrict__ mask,
                  __half* __restrict__ O)
{
    extern __shared__ __half sm_h[];
    __half* Qs = sm_h;                  // 128*72
    __half* Ks = Qs + 128*72;           // 2 stages x 64*72
    __half* Vs = Ks + 2*64*72;          // 2 stages x 64*72
    __half* Ps = Vs + 2*64*72;          // 128*72
    float* redm = (float*)(Ps + 128*72);  // 256
    float* redl = redm + 256;             // 256
    unsigned char* msk = (unsigned char*)(redl + 256);  // 2048
    __shared__ int s_end;

    const int tid = threadIdx.x, lane = tid & 31, wid = tid >> 5;
    const int wm = wid >> 1, wn = wid & 1;       // 4 x 2 warps, 32x32 tiles
    const int grp = lane >> 2, qd = lane & 3;
    const int row_in = lane & 7, mat = lane >> 3;
    const int bh = blockIdx.y, b = bh >> 4, h = bh & 15;
    const int bm = blockIdx.x * 128;

    const __half* qb = Q + b*DMODEL + h*HDIM;
    const __half* kb = K + b*DMODEL + h*HDIM;
    const __half* vb = V + b*DMODEL + h*HDIM;

    const unsigned sQ = (unsigned)__cvta_generic_to_shared(Qs);
    const unsigned sK = (unsigned)__cvta_generic_to_shared(Ks);
    const unsigned sV = (unsigned)__cvta_generic_to_shared(Vs);
    const unsigned sP = (unsigned)__cvta_generic_to_shared(Ps);

    const unsigned aqb = (unsigned)(((wm*32 + (mat&1)*8 + row_in)*72 + (mat>>1)*8)*2);
    const unsigned bkb = (unsigned)(((wn*32 + (mat>>1)*8 + row_in)*72 + (mat&1)*8)*2);
    const unsigned vtb = (unsigned)((((mat&1)*8 + row_in)*72 + wn*32 + (mat>>1)*8)*2);

    const int rkv = tid >> 2, skv = (tid & 3) * 16;

    if (tid == 0) s_end = SLEN;
    // Q tile -> smem (group 1)
    {
        const int r = tid >> 1, sg = (tid & 1) * 32;
        const __half* src = qb + (size_t)(bm + r) * LDAQ + sg;
        const unsigned dst = sQ + (unsigned)((r*72 + sg)*2);
        cp16(dst,      src);
        cp16(dst + 16, src + 8);
        cp16(dst + 32, src + 16);
        cp16(dst + 48, src + 24);
        asm volatile("cp.async.commit_group;" ::: "memory");
    }
    // KV tile 0 -> stage 0 (group 2)
    {
        const __half* ks = kb + (size_t)rkv * LDAQ + skv;
        const __half* vs = vb + (size_t)rkv * LDAQ + skv;
        const unsigned dk = sK + (unsigned)((rkv*72 + skv)*2);
        const unsigned dv = sV + (unsigned)((rkv*72 + skv)*2);
        cp16(dk,      ks); cp16(dk + 16, ks + 8);
        cp16(dv,      vs); cp16(dv + 16, vs + 8);
        asm volatile("cp.async.commit_group;" ::: "memory");
    }
    // mask row -> smem (u8-bool or int32 probed at runtime)
    {
        const unsigned char* m8  = (const unsigned char*)mask;
        const int*           m32 = (const int*)mask;
        const bool isu8 = (m8[SLEN - 1] == 1);
        for (int t = tid; t < SLEN; t += 256)
            msk[t] = isu8 ? (m8[(size_t)b*SLEN + t] != 0)
                          : (m32[(size_t)b*SLEN + t] != 0);
    }
    asm volatile("cp.async.wait_group 0;" ::: "memory");
    __syncthreads();
    {
        int lm = SLEN;
        for (int t = tid; t < SLEN; t += 256)
            if (msk[t]) { lm = t; break; }
        if (lm < SLEN) atomicMin(&s_end, lm);
    }
    __syncthreads();
    const int kv_end = min(SLEN, (s_end + 63) & ~63);

    float m_st[2][2], l_st[2][2];
    float oacc[2][4][4];
#pragma unroll
    for (int mi = 0; mi < 2; mi++) {
        m_st[mi][0] = -INFINITY; m_st[mi][1] = -INFINITY;
        l_st[mi][0] = 0.f;       l_st[mi][1] = 0.f;
#pragma unroll
        for (int ni = 0; ni < 4; ni++)
#pragma unroll
            for (int x = 0; x < 4; x++) oacc[mi][ni][x] = 0.f;
    }

    for (int kt = 0; kt < kv_end; kt += 64) {
        const int st = (kt >> 6) & 1;
        __syncthreads();   // all warps done reading stage st^1 (prev-prev tile)
        // prefetch next tile into stage st^1 (overlaps this tile's compute)
        if (kt + 64 < kv_end) {
            const __half* ks = kb + (size_t)(kt + 64 + rkv) * LDAQ + skv;
            const __half* vs = vb + (size_t)(kt + 64 + rkv) * LDAQ + skv;
            const unsigned dk = sK + (unsigned)((st^1)*KVSTAGE_B) + (unsigned)((rkv*72 + skv)*2);
            const unsigned dv = sV + (unsigned)((st^1)*KVSTAGE_B) + (unsigned)((rkv*72 + skv)*2);
            cp16(dk,      ks); cp16(dk + 16, ks + 8);
            cp16(dv,      vs); cp16(dv + 16, vs + 8);
        }
        asm volatile("cp.async.commit_group;" ::: "memory");
        asm volatile("cp.async.wait_group 1;" ::: "memory");   // this tile's data done
        __syncthreads();

        const unsigned sKst = sK + (unsigned)(st*KVSTAGE_B);
        const unsigned sVst = sV + (unsigned)(st*KVSTAGE_B);

        // S = Q * K^T
        float sacc[2][4][4];
#pragma unroll
        for (int mi = 0; mi < 2; mi++)
#pragma unroll
            for (int ni = 0; ni < 4; ni++)
#pragma unroll
                for (int x = 0; x < 4; x++) sacc[mi][ni][x] = 0.f;
#pragma unroll
        for (int kk = 0; kk < 64; kk += 16) {
            unsigned a[2][4], bb[4][2];
#pragma unroll
            for (int mi = 0; mi < 2; mi++)
                ldm4(a[mi][0], a[mi][1], a[mi][2], a[mi][3],
                     sQ + aqb + (unsigned)(mi*16*72*2 + kk*2));
#pragma unroll
            for (int h2 = 0; h2 < 2; h2++) {
                unsigned q0, q1, q2, q3;
                ldm4(q0, q1, q2, q3, sKst + bkb + (unsigned)(h2*16*72*2 + kk*2));
                bb[2*h2][0] = q0; bb[2*h2][1] = q1;
                bb[2*h2+1][0] = q2; bb[2*h2+1][1] = q3;
            }
#pragma unroll
            for (int mi = 0; mi < 2; mi++)
#pragma unroll
                for (int ni = 0; ni < 4; ni++)
                    mma16(sacc[mi][ni], a[mi], bb[ni][0], bb[ni][1]);
        }
        // mask
#pragma unroll
        for (int ni = 0; ni < 4; ni++) {
            const int c0 = kt + wn*32 + ni*8 + qd*2;
            if (msk[c0]) {
                sacc[0][ni][0] = -INFINITY; sacc[0][ni][2] = -INFINITY;
                sacc[1][ni][0] = -INFINITY; sacc[1][ni][2] = -INFINITY;
            }
            if (msk[c0+1]) {
                sacc[0][ni][1] = -INFINITY; sacc[0][ni][3] = -INFINITY;
                sacc[1][ni][1] = -INFINITY; sacc[1][ni][3] = -INFINITY;
            }
        }
        // row max
#pragma unroll
        for (int mi = 0; mi < 2; mi++)
#pragma unroll
            for (int hf = 0; hf < 2; hf++) {
                float mx = -INFINITY;
#pragma unroll
                for (int ni = 0; ni < 4; ni++)
                    mx = fmaxf(mx, fmaxf(sacc[mi][ni][hf*2], sacc[mi][ni][hf*2+1]));
                mx = fmaxf(mx, __shfl_xor_sync(0xffffffffu, mx, 1));
                mx = fmaxf(mx, __shfl_xor_sync(0xffffffffu, mx, 2));
                if (qd == 0) redm[wn*128 + wm*32 + mi*16 + hf*8 + grp] = mx;
            }
        __syncthreads();

        float sc[2][2];
#pragma unroll
        for (int mi = 0; mi < 2; mi++)
#pragma unroll
            for (int hf = 0; hf < 2; hf++) {
                const int row = wm*32 + mi*16 + hf*8 + grp;
                const float tm = fmaxf(redm[row], redm[128 + row]);
                const float mnew = fmaxf(m_st[mi][hf], tm);
                sc[mi][hf] = __expf(m_st[mi][hf] - mnew);
                m_st[mi][hf] = mnew;
            }
        float ls[2][2] = {{0.f,0.f},{0.f,0.f}};
#pragma unroll
        for (int mi = 0; mi < 2; mi++) {
            const int r = wm*32 + mi*16 + grp;
#pragma unroll
            for (int ni = 0; ni < 4; ni++) {
                const int c = wn*32 + ni*8 + qd*2;
                float p0 = __expf(sacc[mi][ni][0] - m_st[mi][0]);
                float p1 = __expf(sacc[mi][ni][1] - m_st[mi][0]);
                float p2 = __expf(sacc[mi][ni][2] - m_st[mi][1]);
                float p3 = __expf(sacc[mi][ni][3] - m_st[mi][1]);
                ls[mi][0] += p0 + p1;
                ls[mi][1] += p2 + p3;
                *(unsigned*)(Ps + r*72 + c)     = pk2h(p0, p1);
                *(unsigned*)(Ps + (r+8)*72 + c) = pk2h(p2, p3);
            }
        }
#pragma unroll
        for (int mi = 0; mi < 2; mi++)
#pragma unroll
            for (int hf = 0; hf < 2; hf++) {
                float s = ls[mi][hf];
                s += __shfl_xor_sync(0xffffffffu, s, 1);
                s += __shfl_xor_sync(0xffffffffu, s, 2);
                if (qd == 0) redl[wn*128 + wm*32 + mi*16 + hf*8 + grp] = s;
            }
        __syncthreads();
#pragma unroll
        for (int mi = 0; mi < 2; mi++)
#pragma unroll
            for (int hf = 0; hf < 2; hf++) {
                const int row = wm*32 + mi*16 + hf*8 + grp;
                l_st[mi][hf] = l_st[mi][hf] * sc[mi][hf] + redl[row] + redl[128 + row];
            }
#pragma unroll
        for (int mi = 0; mi < 2; mi++)
#pragma unroll
            for (int ni = 0; ni < 4; ni++) {
                oacc[mi][ni][0] *= sc[mi][0]; oacc[mi][ni][1] *= sc[mi][0];
                oacc[mi][ni][2] *= sc[mi][1]; oacc[mi][ni][3] *= sc[mi][1];
            }
        // O += P * V   (V via ldmatrix.trans)
#pragma unroll
        for (int kk = 0; kk < 64; kk += 16) {
            unsigned a[2][4], bb[4][2];
#pragma unroll
            for (int mi = 0; mi < 2; mi++)
                ldm4(a[mi][0], a[mi][1], a[mi][2], a[mi][3],
                     sP + aqb + (unsigned)(mi*16*72*2 + kk*2));
#pragma unroll
            for (int j2 = 0; j2 < 2; j2++) {
                unsigned q0, q1, q2, q3;
                ldm4t(q0, q1, q2, q3, sVst + vtb + (unsigned)(kk*72*2 + j2*32));
                bb[2*j2][0] = q0; bb[2*j2][1] = q1;
                bb[2*j2+1][0] = q2; bb[2*j2+1][1] = q3;
            }
#pragma unroll
            for (int mi = 0; mi < 2; mi++)
#pragma unroll
                for (int ni = 0; ni < 4; ni++)
                    mma16(oacc[mi][ni], a[mi], bb[ni][0], bb[ni][1]);
        }
    }

    // epilogue: O = fp16(O / l)
#pragma unroll
    for (int mi = 0; mi < 2; mi++) {
        const int s0 = bm + wm*32 + mi*16 + grp;
        const float inv0 = 1.f / l_st[mi][0];
        const float inv1 = 1.f / l_st[mi][1];
#pragma unroll
        for (int ni = 0; ni < 4; ni++) {
            const int c = h*HDIM + wn*32 + ni*8 + qd*2;
            __half* o0 = O + ((size_t)s0     * BATCH + b) * DMODEL + c;
            __half* o1 = O + ((size_t)(s0+8) * BATCH + b) * DMODEL + c;
            *(unsigned*)o0 = pk2h(oacc[mi][ni][0]*inv0, oacc[mi][ni][1]*inv0);
            *(unsigned*)o1 = pk2h(oacc[mi][ni][2]*inv1, oacc[mi][ni][3]*inv1);
        }
    }
}

// ---------------------------------------------------------------------------
// out = LayerNorm(y + res) * g + b; optionally also writes fp16 copy.
// ---------------------------------------------------------------------------
template<bool DUAL>
__global__ void add_ln(const float* __restrict__ y, const float* __restrict__ res,
                       const float* __restrict__ g, const float* __restrict__ be,
                       float* __restrict__ out, __half* __restrict__ out_h)
{
    const int r   = blockIdx.x;
    const int tid = threadIdx.x;
    const float4 a  = ((const float4*)(y   + (size_t)r*DMODEL))[tid];
    const float4 b4 = ((const float4*)(res + (size_t)r*DMODEL))[tid];
    float x0 = a.x + b4.x, x1 = a.y + b4.y, x2 = a.z + b4.z, x3 = a.w + b4.w;
    float s = x0 + x1 + x2 + x3;
    float q = x0*x0 + x1*x1 + x2*x2 + x3*x3;

    __shared__ float rs[8], rq[8];
#pragma unroll
    for (int o = 16; o; o >>= 1) {
        s += __shfl_xor_sync(0xffffffffu, s, o);
        q += __shfl_xor_sync(0xffffffffu, q, o);
    }
    if ((tid & 31) == 0) { rs[tid >> 5] = s; rq[tid >> 5] = q; }
    __syncthreads();
    float st = 0.f, qt = 0.f;
#pragma unroll
    for (int i = 0; i < 8; i++) { st += rs[i]; qt += rq[i]; }
    const float mean = st * (1.f/1024.f);
    const float var  = qt * (1.f/1024.f) - mean*mean;
    const float rstd = rsqrtf(var + 1e-5f);

    const float4 gv = ((const float4*)g)[tid];
    const float4 bv = ((const float4*)be)[tid];
    float4 o;
    o.x = (x0 - mean) * rstd * gv.x + bv.x;
    o.y = (x1 - mean) * rstd * gv.y + bv.y;
    o.z = (x2 - mean) * rstd * gv.z + bv.z;
    o.w = (x3 - mean) * rstd * gv.w + bv.w;
    ((float4*)(out + (size_t)r*DMODEL))[tid] = o;
    if (DUAL) {
        uint2 u = make_uint2(pk2h(o.x, o.y), pk2h(o.z, o.w));
        ((uint2*)(out_h + (size_t)r*DMODEL))[tid] = u;
    }
}

// ---------------------------------------------------------------------------
extern "C" void kernel_launch(void* const* d_in, const int* in_sizes, int n_in,
                              void* d_out, int out_size)
{
    const float* state = (const float*)d_in[0];
    const void*  mask  = d_in[1];
    const float* Wq = (const float*)d_in[2];  const float* bq = (const float*)d_in[3];
    const float* Wk = (const float*)d_in[4];  const float* bk = (const float*)d_in[5];
    const float* Wv = (const float*)d_in[6];  const float* bv = (const float*)d_in[7];
    const float* Wo = (const float*)d_in[8];  const float* bo = (const float*)d_in[9];
    const float* g1 = (const float*)d_in[10]; const float* be1 = (const float*)d_in[11];
    const float* W1 = (const float*)d_in[12]; const float* b1 = (const float*)d_in[13];
    const float* W2 = (const float*)d_in[14]; const float* b2 = (const float*)d_in[15];
    const float* g2 = (const float*)d_in[16]; const float* be2 = (const float*)d_in[17];
    float* out = (float*)d_out;

    __half *state_h, *wq_h, *wk_h, *wv_h, *wo_h, *w1_h, *w2_h;
    __half *qh, *kh, *vh, *att_h, *x1_h, *hh;
    float *y, *x1, *y2;
    cudaGetSymbolAddress((void**)&state_h, g_state_h);
    cudaGetSymbolAddress((void**)&wq_h, g_wq_h);
    cudaGetSymbolAddress((void**)&wk_h, g_wk_h);
    cudaGetSymbolAddress((void**)&wv_h, g_wv_h);
    cudaGetSymbolAddress((void**)&wo_h, g_wo_h);
    cudaGetSymbolAddress((void**)&w1_h, g_w1_h);
    cudaGetSymbolAddress((void**)&w2_h, g_w2_h);
    cudaGetSymbolAddress((void**)&qh,  g_qh);
    cudaGetSymbolAddress((void**)&kh,  g_kh);
    cudaGetSymbolAddress((void**)&vh,  g_vh);
    cudaGetSymbolAddress((void**)&att_h, g_att_h);
    cudaGetSymbolAddress((void**)&x1_h, g_x1_h);
    cudaGetSymbolAddress((void**)&hh,  g_hh);
    cudaGetSymbolAddress((void**)&y,   g_y);
    cudaGetSymbolAddress((void**)&x1,  g_x1);
    cudaGetSymbolAddress((void**)&y2,  g_y2);

    cudaFuncSetAttribute(flash_attn_h, cudaFuncAttributeMaxDynamicSharedMemorySize,
                         FLASH_SMEM);
    cudaFuncSetAttribute(gemm_h<0>, cudaFuncAttributeMaxDynamicSharedMemorySize, G_SMEM);
    cudaFuncSetAttribute(gemm_h<1>, cudaFuncAttributeMaxDynamicSharedMemorySize, G_SMEM);
    cudaFuncSetAttribute(gemm_h<2>, cudaFuncAttributeMaxDynamicSharedMemorySize, G_SMEM);
    cudaFuncSetAttribute(gemm_qkv_h, cudaFuncAttributeMaxDynamicSharedMemorySize, G_SMEM);

    // single-launch converts (state + all 6 weights); z=0 needs 4096 blocks
    f2h_all<<<dim3(4096, 1, 7), 256>>>(state, state_h, Wq, wq_h, Wk, wk_h,
                                       Wv, wv_h, Wo, wo_h, W1, w1_h, W2, w2_h);
    // fused QKV projection (fp16 out; q pre-scaled by 1/8)
    gemm_qkv_h<<<dim3(DMODEL/128, NROW/128, 3), 256, G_SMEM>>>(
        state_h, wq_h, wk_h, wv_h, bq, bk, bv, qh, kh, vh);
    // fused attention -> fp16 output
    flash_attn_h<<<dim3(SLEN/128, BATCH*NHEAD), 256, FLASH_SMEM>>>(qh, kh, vh, mask, att_h);
    // output projection + LN1 (dual write)
    gemm_h<0><<<dim3(DMODEL/128, NROW/128), 256, G_SMEM>>>(att_h, wo_h, bo, y, DMODEL, DMODEL);
    add_ln<true><<<NROW, 256>>>(y, state, g1, be1, x1, x1_h);
    // FFN (FF1 fp16+ReLU) + LN2
    gemm_h<2><<<dim3(FFDIM/128, NROW/128), 256, G_SMEM>>>(x1_h, w1_h, b1, hh, FFDIM, DMODEL);
    gemm_h<0><<<dim3(DMODEL/128, NROW/128), 256, G_SMEM>>>(hh, w2_h, b2, y2, DMODEL, FFDIM);
    add_ln<false><<<NROW, 256>>>(y2, x1, g2, be2, out, nullptr);
}